// round 2
// baseline (speedup 1.0000x reference)
#include <cuda_runtime.h>
#include <cuda_bf16.h>

// Shapes
#define BB 8
#define P0 20000
#define P1 5000
#define P2 1250
#define MM 10
#define WW 9
#define C0 3
#define C1 64
#define C2 128
#define LATENT 256
#define FDIM (P2*C2)      // 160000
#define KA3 (WW*C1)       // 576
#define NROWS (BB*P1)     // 40000

// ---------------- scratch (device globals; no allocation) ----------------
__device__ float g_h1[BB*P0*C1];        // 10.24M
__device__ float g_h2[BB*P1*C1];        // 2.56M
__device__ float g_s2[NROWS*KA3];       // 23.04M
__device__ float g_h3[BB*P1*C2];        // 5.12M
__device__ float g_h4[BB*P2*C2];        // 1.28M  == f
__device__ float g_Bt[KA3*C2];          // 73728
#define SPLITK 20
__device__ float g_part[SPLITK*512*BB];

__device__ __forceinline__ float eluf(float x){
    return x > 0.f ? x : (expf(x) - 1.f);
}

// ---------------- packed f32x2 helpers ----------------
__device__ __forceinline__ unsigned long long pk2(float lo, float hi){
    unsigned long long r;
    asm("mov.b64 %0, {%1,%2};" : "=l"(r) : "f"(lo), "f"(hi));
    return r;
}
__device__ __forceinline__ void fma2(unsigned long long &d, unsigned long long a, unsigned long long b){
    asm("fma.rn.f32x2 %0, %1, %2, %0;" : "+l"(d) : "l"(a), "l"(b));
}
__device__ __forceinline__ float2 upk2(unsigned long long v){
    float2 f;
    asm("mov.b64 {%0,%1}, %2;" : "=f"(f.x), "=f"(f.y) : "l"(v));
    return f;
}

// ---------------- stage 1: full_conv0 + elu ----------------
// out[b,p,o] = elu( bias0[o] + sum_{w,i} weights0[w, o*3+i] * s[b,p,w,i] )
// s[b,p,w,i] = sum_m w2[p,m,w] * x[b, nb0[p,m], i]
__global__ void __launch_bounds__(256) k_conv0(
    const float* __restrict__ x, const int* __restrict__ nb0,
    const float* __restrict__ w0, const float* __restrict__ bias0,
    const float* __restrict__ ww0, float* __restrict__ h1)
{
    const int PTS = 4;
    __shared__ float sw0[WW*C1*C0];            // 1728
    __shared__ float nbh[PTS][BB][MM][C0];     // 960
    __shared__ float w2s[PTS][MM][WW];         // 360
    __shared__ float ssh[PTS][BB][28];         // padded 27->28
    __shared__ int   nbs[PTS][MM];

    const int tid = threadIdx.x;
    const int p0 = blockIdx.x * PTS;

    for (int i = tid; i < WW*C1*C0; i += 256) sw0[i] = w0[i];

    if (tid < PTS*MM) {
        int pt = tid / MM, m = tid % MM;
        int nb = nb0[(p0+pt)*MM + m];
        bool valid = (nb != P0);
        nbs[pt][m] = valid ? nb : 0;
        const float* wp = ww0 + ((long)(p0+pt)*MM + m)*WW;
        #pragma unroll
        for (int w = 0; w < WW; w++) w2s[pt][m][w] = valid ? wp[w] : 0.f;
    }
    __syncthreads();

    for (int idx = tid; idx < PTS*BB*MM; idx += 256) {
        int pt = idx / (BB*MM); int rem = idx % (BB*MM);
        int b = rem / MM, m = rem % MM;
        const float* xr = x + ((long)b*P0 + nbs[pt][m]) * C0;
        nbh[pt][b][m][0] = xr[0];
        nbh[pt][b][m][1] = xr[1];
        nbh[pt][b][m][2] = xr[2];
    }
    __syncthreads();

    for (int idx = tid; idx < PTS*BB*27; idx += 256) {
        int pt = idx / (BB*27); int rem = idx % (BB*27);
        int b = rem / 27, k = rem % 27;
        int w = k / 3, i = k % 3;
        float acc = 0.f;
        #pragma unroll
        for (int m = 0; m < MM; m++) acc += w2s[pt][m][w] * nbh[pt][b][m][i];
        ssh[pt][b][k] = acc;
    }
    __syncthreads();

    const int o = tid & 63;
    float wr[27];
    #pragma unroll
    for (int k = 0; k < 27; k++) {
        int w = k / 3, i = k % 3;
        wr[k] = sw0[w*(C1*C0) + o*3 + i];
    }
    const float bv = bias0[o];
    const int pairbase = tid >> 6; // 0..3
    #pragma unroll
    for (int j = 0; j < 8; j++) {
        int pair = pairbase + j*4;     // 0..31
        int pt = pair >> 3, b = pair & 7;
        float acc = bv;
        #pragma unroll
        for (int k = 0; k < 27; k++) acc += wr[k] * ssh[pt][b][k];
        h1[((long)b*P0 + p0 + pt)*C1 + o] = eluf(acc);
    }
}

// ---------------- stage 2: pool1 + elu ----------------
__global__ void __launch_bounds__(128) k_pool1(
    const float* __restrict__ h1, const int* __restrict__ nb1,
    const float* __restrict__ pnb, float* __restrict__ h2)
{
    __shared__ float pn[MM];
    __shared__ int nbs[MM];
    const int p = blockIdx.x, tid = threadIdx.x;
    if (tid < MM) {
        int nb = nb1[p*MM + tid];
        bool valid = (nb != P0);
        nbs[tid] = valid ? nb : 0;
        pn[tid]  = valid ? fabsf(pnb[p*MM + tid]) : 0.f;
    }
    __syncthreads();
    float den = 1e-8f;
    #pragma unroll
    for (int m = 0; m < MM; m++) den += pn[m];
    const float inv = 1.f / den;

    for (int idx = tid; idx < BB*C1; idx += 128) {
        int b = idx >> 6, c = idx & 63;
        float acc = 0.f;
        #pragma unroll
        for (int m = 0; m < MM; m++)
            acc += pn[m] * h1[((long)b*P0 + nbs[m])*C1 + c];
        h2[((long)b*P1 + p)*C1 + c] = eluf(acc * inv);
    }
}

// ---------------- stage 3a: s2[b*P1+p][w*64+i] ----------------
__global__ void __launch_bounds__(256) k_s2(
    const float* __restrict__ h2, const int* __restrict__ nb2,
    const float* __restrict__ ww2, float* __restrict__ s2)
{
    __shared__ float nbh[BB][MM][C1];  // 20KB
    __shared__ float w2s[MM][WW];
    __shared__ int nbs[MM];
    const int p = blockIdx.x, tid = threadIdx.x;
    if (tid < MM) {
        int nb = nb2[p*MM + tid];
        nbs[tid] = (nb != P1) ? nb : -1;
    }
    __syncthreads();
    if (tid < MM*WW) {
        int m = tid / WW, w = tid % WW;
        w2s[m][w] = (nbs[m] >= 0) ? ww2[((long)p*MM + m)*WW + w] : 0.f;
    }
    for (int idx = tid; idx < BB*MM*C1; idx += 256) {
        int b = idx / (MM*C1); int rem = idx % (MM*C1);
        int m = rem / C1, i = rem & 63;
        int nb = nbs[m];
        nbh[b][m][i] = (nb >= 0) ? h2[((long)b*P1 + nb)*C1 + i] : 0.f;
    }
    __syncthreads();
    for (int idx = tid; idx < BB*KA3; idx += 256) {
        int b = idx / KA3, k = idx % KA3;
        int w = k >> 6, i = k & 63;
        float acc = 0.f;
        #pragma unroll
        for (int m = 0; m < MM; m++) acc += w2s[m][w] * nbh[b][m][i];
        s2[(long)(b*P1 + p)*KA3 + k] = acc;
    }
}

// ---------------- weights2 transpose: Bt[(w*64+i)*128 + o] ----------------
__global__ void k_tw2(const float* __restrict__ w2g, float* __restrict__ Bt){
    int k = blockIdx.x;   // 576
    int o = threadIdx.x;  // 128
    int w = k >> 6, i = k & 63;
    Bt[k*C2 + o] = w2g[w*(C2*C1) + o*C1 + i];
}

// ---------------- stage 3b: C[40000x128] = A[40000x576] x Bt + bias + elu ----------------
#define BM 64
#define BN 128
#define BK 16
__global__ void __launch_bounds__(256) k_gemm3b(
    const float* __restrict__ A, const float* __restrict__ Bt,
    const float* __restrict__ bias, float* __restrict__ Cout)
{
    __shared__ float As[BK][68];   // transposed, padded (272B rows, 16B aligned)
    __shared__ float Bs[BK][BN];
    const int tid = threadIdx.x;
    const int r0 = blockIdx.x * BM;
    const int trow = (tid >> 4) << 2;  // 0..60
    const int tcol = (tid & 15) << 3;  // 0..120

    unsigned long long acc[16];
    #pragma unroll
    for (int i = 0; i < 16; i++) acc[i] = 0ULL;

    const int ar = tid >> 2, ak = (tid & 3) << 2;
    const int bk = tid >> 5, bo = (tid & 31) << 2;

    for (int kt = 0; kt < KA3; kt += BK) {
        float4 av  = *(const float4*)(A  + (long)(r0 + ar)*KA3 + kt + ak);
        float4 bv0 = *(const float4*)(Bt + (kt + bk    )*BN + bo);
        float4 bv1 = *(const float4*)(Bt + (kt + bk + 8)*BN + bo);
        __syncthreads();
        As[ak  ][ar] = av.x;
        As[ak+1][ar] = av.y;
        As[ak+2][ar] = av.z;
        As[ak+3][ar] = av.w;
        *(float4*)&Bs[bk    ][bo] = bv0;
        *(float4*)&Bs[bk + 8][bo] = bv1;
        __syncthreads();
        #pragma unroll
        for (int kk = 0; kk < BK; kk++) {
            float4 a  = *(const float4*)&As[kk][trow];
            float4 b0 = *(const float4*)&Bs[kk][tcol];
            float4 b1 = *(const float4*)&Bs[kk][tcol + 4];
            unsigned long long pb0 = pk2(b0.x, b0.y);
            unsigned long long pb1 = pk2(b0.z, b0.w);
            unsigned long long pb2 = pk2(b1.x, b1.y);
            unsigned long long pb3 = pk2(b1.z, b1.w);
            unsigned long long pa0 = pk2(a.x, a.x);
            unsigned long long pa1 = pk2(a.y, a.y);
            unsigned long long pa2 = pk2(a.z, a.z);
            unsigned long long pa3 = pk2(a.w, a.w);
            fma2(acc[ 0], pa0, pb0); fma2(acc[ 1], pa0, pb1);
            fma2(acc[ 2], pa0, pb2); fma2(acc[ 3], pa0, pb3);
            fma2(acc[ 4], pa1, pb0); fma2(acc[ 5], pa1, pb1);
            fma2(acc[ 6], pa1, pb2); fma2(acc[ 7], pa1, pb3);
            fma2(acc[ 8], pa2, pb0); fma2(acc[ 9], pa2, pb1);
            fma2(acc[10], pa2, pb2); fma2(acc[11], pa2, pb3);
            fma2(acc[12], pa3, pb0); fma2(acc[13], pa3, pb1);
            fma2(acc[14], pa3, pb2); fma2(acc[15], pa3, pb3);
        }
    }
    #pragma unroll
    for (int i = 0; i < 4; i++) {
        int r = r0 + trow + i;
        #pragma unroll
        for (int c = 0; c < 4; c++) {
            float2 v = upk2(acc[i*4 + c]);
            int col = tcol + c*2;
            float o0 = eluf(v.x + bias[col]);
            float o1 = eluf(v.y + bias[col + 1]);
            float2 st = make_float2(o0, o1);
            *(float2*)&Cout[(long)r*BN + col] = st;
        }
    }
}

// ---------------- stage 4: pool3 + elu ----------------
__global__ void __launch_bounds__(128) k_pool3(
    const float* __restrict__ h3, const int* __restrict__ nb3,
    const float* __restrict__ pnb, float* __restrict__ h4)
{
    __shared__ float pn[MM];
    __shared__ int nbs[MM];
    const int p = blockIdx.x, tid = threadIdx.x;
    if (tid < MM) {
        int nb = nb3[p*MM + tid];
        bool valid = (nb != P1);
        nbs[tid] = valid ? nb : 0;
        pn[tid]  = valid ? fabsf(pnb[p*MM + tid]) : 0.f;
    }
    __syncthreads();
    float den = 1e-8f;
    #pragma unroll
    for (int m = 0; m < MM; m++) den += pn[m];
    const float inv = 1.f / den;
    const int c = tid; // 128
    #pragma unroll
    for (int b = 0; b < BB; b++) {
        float acc = 0.f;
        #pragma unroll
        for (int m = 0; m < MM; m++)
            acc += pn[m] * h3[((long)b*P1 + nbs[m])*C2 + c];
        h4[((long)b*P2 + p)*C2 + c] = eluf(acc * inv);
    }
}

// ---------------- stage 5: dense head, split-K partials ----------------
#define CHK 800
#define FSTRIDE 804   // 804 % 32 == 4 -> b*FSTRIDE hits 8 distinct banks
__global__ void __launch_bounds__(256) k_dense(
    const float* __restrict__ Wm, const float* __restrict__ Ws,
    const float* __restrict__ f, float* __restrict__ part)
{
    __shared__ float fs[BB*FSTRIDE];
    const int tid = threadIdx.x;
    const int rg = blockIdx.x & 15;
    const int sk = blockIdx.x >> 4;     // 0..SPLITK-1
    const int l = rg*32 + (tid >> 3);   // 0..511
    const int b = tid & 7;
    const float* Wrow = (l < LATENT) ? (Wm + (long)l*FDIM)
                                     : (Ws + (long)(l - LATENT)*FDIM);
    const int kbase = sk * (FDIM / SPLITK);   // 8000 per split
    float acc = 0.f;
    for (int c0 = 0; c0 < FDIM/SPLITK; c0 += CHK) {
        __syncthreads();
        for (int idx = tid; idx < BB*CHK; idx += 256) {
            int bb = idx / CHK, k = idx % CHK;
            fs[bb*FSTRIDE + k] = f[(long)bb*FDIM + kbase + c0 + k];
        }
        __syncthreads();
        const float* wp = Wrow + kbase + c0;
        const float* fb = fs + b*FSTRIDE;
        #pragma unroll 2
        for (int k = 0; k < CHK; k += 4) {
            float4 w4 = *(const float4*)(wp + k);
            acc += w4.x * fb[k + 0];
            acc += w4.y * fb[k + 1];
            acc += w4.z * fb[k + 2];
            acc += w4.w * fb[k + 3];
        }
    }
    part[(sk*512 + l)*BB + b] = acc;
}

__global__ void __launch_bounds__(256) k_reduce(
    const float* __restrict__ part, const float* __restrict__ bm,
    const float* __restrict__ bs, float* __restrict__ out)
{
    int idx = blockIdx.x*256 + threadIdx.x;   // 4096
    int l = idx >> 3, b = idx & 7;
    float acc = (l < LATENT) ? bm[l] : bs[l - LATENT];
    #pragma unroll
    for (int sk = 0; sk < SPLITK; sk++) acc += part[(sk*512 + l)*BB + b];
    out[b*512 + l] = acc;
}

// ---------------- launch ----------------
extern "C" void kernel_launch(void* const* d_in, const int* in_sizes, int n_in,
                              void* d_out, int out_size)
{
    const float* x      = (const float*)d_in[0];
    const int*   nb0    = (const int*)  d_in[1];
    const int*   nb1    = (const int*)  d_in[2];
    const int*   nb2    = (const int*)  d_in[3];
    const int*   nb3    = (const int*)  d_in[4];
    const float* w0     = (const float*)d_in[5];
    const float* bias0  = (const float*)d_in[6];
    const float* ww0    = (const float*)d_in[7];
    const float* pnb1   = (const float*)d_in[8];
    const float* w2     = (const float*)d_in[9];
    const float* bias2  = (const float*)d_in[10];
    const float* ww2    = (const float*)d_in[11];
    const float* pnb3   = (const float*)d_in[12];
    const float* Wm     = (const float*)d_in[13];
    const float* bm     = (const float*)d_in[14];
    const float* Ws     = (const float*)d_in[15];
    const float* bs     = (const float*)d_in[16];
    float* out = (float*)d_out;

    float *h1, *h2, *s2, *h3, *h4, *Bt, *part;
    cudaGetSymbolAddress((void**)&h1,   g_h1);
    cudaGetSymbolAddress((void**)&h2,   g_h2);
    cudaGetSymbolAddress((void**)&s2,   g_s2);
    cudaGetSymbolAddress((void**)&h3,   g_h3);
    cudaGetSymbolAddress((void**)&h4,   g_h4);
    cudaGetSymbolAddress((void**)&Bt,   g_Bt);
    cudaGetSymbolAddress((void**)&part, g_part);

    k_tw2   <<<KA3, C2>>>(w2, Bt);
    k_conv0 <<<P0/4, 256>>>(x, nb0, w0, bias0, ww0, h1);
    k_pool1 <<<P1, 128>>>(h1, nb1, pnb1, h2);
    k_s2    <<<P1, 256>>>(h2, nb2, ww2, s2);
    k_gemm3b<<<NROWS/BM, 256>>>(s2, Bt, bias2, h3);
    k_pool3 <<<P2, 128>>>(h3, nb3, pnb3, h4);
    k_dense <<<16*SPLITK, 256>>>(Wm, Ws, h4, part);
    k_reduce<<<16, 256>>>(part, bm, bs, out);
}

// round 4
// speedup vs baseline: 1.3514x; 1.3514x over previous
#include <cuda_runtime.h>
#include <cuda_bf16.h>

// Shapes
#define BB 8
#define P0 20000
#define P1 5000
#define P2 1250
#define MM 10
#define WW 9
#define C0 3
#define C1 64
#define C2 128
#define LATENT 256
#define FDIM (P2*C2)      // 160000
#define KA3 (WW*C1)       // 576
#define NROWS (BB*P1)     // 40000

typedef unsigned long long ull;

// ---------------- scratch (device globals; no allocation) ----------------
__device__ float g_h1[BB*P0*C1];        // 10.24M
__device__ float g_h2[BB*P1*C1];        // 2.56M
__device__ float g_h3[BB*P1*C2];        // 5.12M
__device__ float g_ft[FDIM*BB];         // 1.28M  (f transposed: [k][b])
__device__ float g_Bt[KA3*C2];          // 73728
#define SPLITD 100
#define DKS    1600                      // FDIM / SPLITD
__device__ float g_part[SPLITD*512*BB];  // 409600

__device__ __forceinline__ float eluf(float x){
    return x > 0.f ? x : (expf(x) - 1.f);
}

// ---------------- packed f32x2 helpers ----------------
__device__ __forceinline__ ull pk2(float lo, float hi){
    ull r;
    asm("mov.b64 %0, {%1,%2};" : "=l"(r) : "f"(lo), "f"(hi));
    return r;
}
__device__ __forceinline__ void fma2(ull &d, ull a, ull b){
    asm("fma.rn.f32x2 %0, %1, %2, %0;" : "+l"(d) : "l"(a), "l"(b));
}
__device__ __forceinline__ ull add2(ull a, ull b){
    ull r;
    asm("add.rn.f32x2 %0, %1, %2;" : "=l"(r) : "l"(a), "l"(b));
    return r;
}
__device__ __forceinline__ float2 upk2(ull v){
    float2 f;
    asm("mov.b64 {%0,%1}, %2;" : "=f"(f.x), "=f"(f.y) : "l"(v));
    return f;
}

// ---------------- stage 1: full_conv0 + elu ----------------
__global__ void __launch_bounds__(256) k_conv0(
    const float* __restrict__ x, const int* __restrict__ nb0,
    const float* __restrict__ w0, const float* __restrict__ bias0,
    const float* __restrict__ ww0, float* __restrict__ h1)
{
    const int PTS = 4;
    __shared__ float sw0[WW*C1*C0];            // 1728
    __shared__ float nbh[PTS][BB][MM][C0];     // 960
    __shared__ float w2s[PTS][MM][WW];         // 360
    __shared__ float ssh[PTS][BB][28];         // padded 27->28
    __shared__ int   nbs[PTS][MM];

    const int tid = threadIdx.x;
    const int p0 = blockIdx.x * PTS;

    for (int i = tid; i < WW*C1*C0; i += 256) sw0[i] = w0[i];

    if (tid < PTS*MM) {
        int pt = tid / MM, m = tid % MM;
        int nb = nb0[(p0+pt)*MM + m];
        bool valid = (nb != P0);
        nbs[pt][m] = valid ? nb : 0;
        const float* wp = ww0 + ((long)(p0+pt)*MM + m)*WW;
        #pragma unroll
        for (int w = 0; w < WW; w++) w2s[pt][m][w] = valid ? wp[w] : 0.f;
    }
    __syncthreads();

    for (int idx = tid; idx < PTS*BB*MM; idx += 256) {
        int pt = idx / (BB*MM); int rem = idx % (BB*MM);
        int b = rem / MM, m = rem % MM;
        const float* xr = x + ((long)b*P0 + nbs[pt][m]) * C0;
        nbh[pt][b][m][0] = xr[0];
        nbh[pt][b][m][1] = xr[1];
        nbh[pt][b][m][2] = xr[2];
    }
    __syncthreads();

    for (int idx = tid; idx < PTS*BB*27; idx += 256) {
        int pt = idx / (BB*27); int rem = idx % (BB*27);
        int b = rem / 27, k = rem % 27;
        int w = k / 3, i = k % 3;
        float acc = 0.f;
        #pragma unroll
        for (int m = 0; m < MM; m++) acc += w2s[pt][m][w] * nbh[pt][b][m][i];
        ssh[pt][b][k] = acc;
    }
    __syncthreads();

    const int o = tid & 63;
    float wr[27];
    #pragma unroll
    for (int k = 0; k < 27; k++) {
        int w = k / 3, i = k % 3;
        wr[k] = sw0[w*(C1*C0) + o*3 + i];
    }
    const float bv = bias0[o];
    const int pairbase = tid >> 6; // 0..3
    #pragma unroll
    for (int j = 0; j < 8; j++) {
        int pair = pairbase + j*4;     // 0..31
        int pt = pair >> 3, b = pair & 7;
        float acc = bv;
        #pragma unroll
        for (int k = 0; k < 27; k++) acc += wr[k] * ssh[pt][b][k];
        h1[((long)b*P0 + p0 + pt)*C1 + o] = eluf(acc);
    }
}

// ---------------- stage 2: pool1 + elu ----------------
__global__ void __launch_bounds__(128) k_pool1(
    const float* __restrict__ h1, const int* __restrict__ nb1,
    const float* __restrict__ pnb, float* __restrict__ h2)
{
    __shared__ float pn[MM];
    __shared__ int nbs[MM];
    const int p = blockIdx.x, tid = threadIdx.x;
    if (tid < MM) {
        int nb = nb1[p*MM + tid];
        bool valid = (nb != P0);
        nbs[tid] = valid ? nb : 0;
        pn[tid]  = valid ? fabsf(pnb[p*MM + tid]) : 0.f;
    }
    __syncthreads();
    float den = 1e-8f;
    #pragma unroll
    for (int m = 0; m < MM; m++) den += pn[m];
    const float inv = 1.f / den;

    for (int idx = tid; idx < BB*C1; idx += 128) {
        int b = idx >> 6, c = idx & 63;
        float acc = 0.f;
        #pragma unroll
        for (int m = 0; m < MM; m++)
            acc += pn[m] * h1[((long)b*P0 + nbs[m])*C1 + c];
        h2[((long)b*P1 + p)*C1 + c] = eluf(acc * inv);
    }
}

// ---------------- weights2 transpose: Bt[(w*64+i)*128 + o] ----------------
__global__ void k_tw2(const float* __restrict__ w2g, float* __restrict__ Bt){
    int k = blockIdx.x;   // 576
    int o = threadIdx.x;  // 128
    int w = k >> 6, i = k & 63;
    Bt[k*C2 + o] = w2g[w*(C2*C1) + o*C1 + i];
}

// ---------------- fused stage 3: gather+conv2 GEMM + bias + elu ----------------
// C[r, o] = elu(bias[o] + sum_k As[r,k]*Bt[k,o]),
// As[r, w*64+i] = sum_m w2[p,m,w]*h2[b, nb2[p,m], i],  r = b*P1 + p
#define GBM 64
#define GBN 128
// smem floats: w2 5760 | nbh 10240 | As 16*68=1088 | Bs 16*128=2048 | off 640 ints
#define SM_W2   0
#define SM_NBH  5760
#define SM_AS   (5760+10240)
#define SM_BS   (SM_AS+1088)
#define SM_OFF  (SM_BS+2048)
#define CONV2_SMEM ((SM_OFF + 640) * 4)

__global__ void __launch_bounds__(256) k_conv2(
    const float* __restrict__ h2, const int* __restrict__ nb2,
    const float* __restrict__ ww2, const float* __restrict__ Bt,
    const float* __restrict__ bias, float* __restrict__ Cout)
{
    extern __shared__ float sm[];
    float* s_w2  = sm + SM_W2;
    float* s_nbh = sm + SM_NBH;
    float* s_As  = sm + SM_AS;
    float* s_Bs  = sm + SM_BS;
    int*   s_off = (int*)(sm + SM_OFF);

    const int tid = threadIdx.x;
    const int r0 = blockIdx.x * GBM;

    // per-(row,m) gather offsets + validity
    for (int e = tid; e < GBM*MM; e += 256) {
        int pl = e / MM, m = e - pl*MM;
        int r = r0 + pl; int b = r / P1; int p = r - b*P1;
        int nb = nb2[p*MM + m];
        s_off[e] = (nb != P1) ? (b*P1 + nb)*C1 : -1;
    }
    __syncthreads();
    // per-row w2 weights, masked
    for (int e = tid; e < GBM*MM*WW; e += 256) {
        int pl = e / (MM*WW); int rem = e - pl*(MM*WW);
        int m = rem / WW, w = rem - m*WW;
        int r = r0 + pl; int b = r / P1; int p = r - b*P1;
        s_w2[e] = (s_off[pl*MM+m] >= 0) ? ww2[((long)p*MM + m)*WW + w] : 0.f;
    }

    const int trow = (tid >> 4) << 2;  // 0..60
    const int tcol = (tid & 15) << 3;  // 0..120
    ull acc[16];
    #pragma unroll
    for (int i = 0; i < 16; i++) acc[i] = 0ULL;

    const int bk = tid >> 5, bo = (tid & 31) << 2;

    for (int ic = 0; ic < 4; ic++) {
        __syncthreads();
        // gather nbh chunk: [m][pl][i(16)]
        for (int e = tid; e < MM*GBM*4; e += 256) {
            int m = e >> 8; int rem = e & 255;
            int pl = rem >> 2, i4 = rem & 3;
            int off = s_off[pl*MM + m];
            float4 v = make_float4(0.f,0.f,0.f,0.f);
            if (off >= 0) v = *(const float4*)(h2 + (long)off + ic*16 + i4*4);
            *(float4*)(s_nbh + (m*GBM + pl)*16 + i4*4) = v;
        }
        __syncthreads();

        for (int w = 0; w < WW; w++) {
            // stage Bs rows from global (L2-resident Bt)
            const int krow = w*64 + ic*16;
            float4 bv0 = *(const float4*)(Bt + (krow + bk    )*GBN + bo);
            float4 bv1 = *(const float4*)(Bt + (krow + bk + 8)*GBN + bo);
            __syncthreads();   // previous main-loop readers done
            // build As[i][pl]
            #pragma unroll
            for (int q = 0; q < 4; q++) {
                int e = tid + q*256;      // 0..1023
                int i = e & 15, pl = e >> 4;
                float a = 0.f;
                #pragma unroll
                for (int m = 0; m < MM; m++)
                    a += s_w2[(pl*MM + m)*WW + w] * s_nbh[(m*GBM + pl)*16 + i];
                s_As[i*68 + pl] = a;
            }
            *(float4*)(s_Bs + (bk    )*GBN + bo) = bv0;
            *(float4*)(s_Bs + (bk + 8)*GBN + bo) = bv1;
            __syncthreads();

            #pragma unroll
            for (int kk = 0; kk < 16; kk++) {
                float4 a  = *(const float4*)(s_As + kk*68 + trow);
                float4 b0 = *(const float4*)(s_Bs + kk*GBN + tcol);
                float4 b1 = *(const float4*)(s_Bs + kk*GBN + tcol + 4);
                ull pb0 = pk2(b0.x, b0.y);
                ull pb1 = pk2(b0.z, b0.w);
                ull pb2 = pk2(b1.x, b1.y);
                ull pb3 = pk2(b1.z, b1.w);
                ull pa0 = pk2(a.x, a.x);
                ull pa1 = pk2(a.y, a.y);
                ull pa2 = pk2(a.z, a.z);
                ull pa3 = pk2(a.w, a.w);
                fma2(acc[ 0], pa0, pb0); fma2(acc[ 1], pa0, pb1);
                fma2(acc[ 2], pa0, pb2); fma2(acc[ 3], pa0, pb3);
                fma2(acc[ 4], pa1, pb0); fma2(acc[ 5], pa1, pb1);
                fma2(acc[ 6], pa1, pb2); fma2(acc[ 7], pa1, pb3);
                fma2(acc[ 8], pa2, pb0); fma2(acc[ 9], pa2, pb1);
                fma2(acc[10], pa2, pb2); fma2(acc[11], pa2, pb3);
                fma2(acc[12], pa3, pb0); fma2(acc[13], pa3, pb1);
                fma2(acc[14], pa3, pb2); fma2(acc[15], pa3, pb3);
            }
        }
    }

    #pragma unroll
    for (int i = 0; i < 4; i++) {
        int r = r0 + trow + i;
        #pragma unroll
        for (int c = 0; c < 4; c++) {
            float2 v = upk2(acc[i*4 + c]);
            int col = tcol + c*2;
            float o0 = eluf(v.x + bias[col]);
            float o1 = eluf(v.y + bias[col + 1]);
            *(float2*)&Cout[(long)r*GBN + col] = make_float2(o0, o1);
        }
    }
}

// ---------------- stage 4: pool3 + elu, writes f TRANSPOSED ft[k][b] ----------------
__global__ void __launch_bounds__(128) k_pool3(
    const float* __restrict__ h3, const int* __restrict__ nb3,
    const float* __restrict__ pnb, float* __restrict__ ft)
{
    __shared__ float pn[MM];
    __shared__ int nbs[MM];
    const int p = blockIdx.x, tid = threadIdx.x;
    if (tid < MM) {
        int nb = nb3[p*MM + tid];
        bool valid = (nb != P1);
        nbs[tid] = valid ? nb : 0;
        pn[tid]  = valid ? fabsf(pnb[p*MM + tid]) : 0.f;
    }
    __syncthreads();
    float den = 1e-8f;
    #pragma unroll
    for (int m = 0; m < MM; m++) den += pn[m];
    const float inv = 1.f / den;
    const int c = tid; // 128
    float out[BB];
    #pragma unroll
    for (int b = 0; b < BB; b++) {
        float acc = 0.f;
        #pragma unroll
        for (int m = 0; m < MM; m++)
            acc += pn[m] * h3[((long)b*P1 + nbs[m])*C2 + c];
        out[b] = eluf(acc * inv);
    }
    float4* d = (float4*)(ft + ((long)p*C2 + c)*BB);
    d[0] = make_float4(out[0], out[1], out[2], out[3]);
    d[1] = make_float4(out[4], out[5], out[6], out[7]);
}

// ---------------- stage 5: dense head ----------------
// ft[k][b]; warp handles 4 W rows; lane = (kl 0..15, b-half).
// Each lane accumulates k = {kl, kl+16, ...}; cross-lane butterfly reduction
// over the kl bits (lane bits 1..4) before the write.
__global__ void __launch_bounds__(256) k_dense(
    const float* __restrict__ Wm, const float* __restrict__ Ws,
    const float* __restrict__ ft, float* __restrict__ part)
{
    extern __shared__ float fs[];   // DKS*8 floats
    const int tid = threadIdx.x;
    const int rb = blockIdx.x & 15;      // 0..15  (32 rows each)
    const int sk = blockIdx.x >> 4;      // 0..SPLITD-1
    const int kbase = sk * DKS;

    // stage ft chunk: contiguous copy
    {
        const float4* src = (const float4*)(ft + (long)kbase*BB);
        float4* dst = (float4*)fs;
        for (int i = tid; i < DKS*BB/4; i += 256) dst[i] = src[i];
    }
    __syncthreads();

    const int warp = tid >> 5, lane = tid & 31;
    const int l0 = rb*32 + warp*4;
    const float* Wb = (l0 < LATENT) ? (Wm + (long)l0*FDIM)
                                    : (Ws + (long)(l0 - LATENT)*FDIM);
    const float* W0 = Wb;
    const float* W1 = Wb + FDIM;
    const float* W2p = Wb + 2L*FDIM;
    const float* W3 = Wb + 3L*FDIM;

    const int kl = lane >> 1;      // 0..15
    const int h  = lane & 1;       // b-half
    const float* fpb = fs + h*4;

    ull a00=0,a01=0,a10=0,a11=0,a20=0,a21=0,a30=0,a31=0;

    #pragma unroll 2
    for (int t = 0; t < DKS/16; t++) {
        int k = t*16 + kl;
        float4 fv = *(const float4*)(fpb + k*8);
        ull f01 = pk2(fv.x, fv.y);
        ull f23 = pk2(fv.z, fv.w);
        long kg = kbase + k;
        float w0 = W0[kg], w1 = W1[kg], w2v = W2p[kg], w3 = W3[kg];
        ull p0 = pk2(w0,w0), p1 = pk2(w1,w1), p2 = pk2(w2v,w2v), p3 = pk2(w3,w3);
        fma2(a00,p0,f01); fma2(a01,p0,f23);
        fma2(a10,p1,f01); fma2(a11,p1,f23);
        fma2(a20,p2,f01); fma2(a21,p2,f23);
        fma2(a30,p3,f01); fma2(a31,p3,f23);
    }

    // butterfly reduction across kl (lane bits 1..4); h bit (bit 0) untouched
    #pragma unroll
    for (int ofs = 2; ofs < 32; ofs <<= 1) {
        a00 = add2(a00, __shfl_xor_sync(0xffffffffu, a00, ofs));
        a01 = add2(a01, __shfl_xor_sync(0xffffffffu, a01, ofs));
        a10 = add2(a10, __shfl_xor_sync(0xffffffffu, a10, ofs));
        a11 = add2(a11, __shfl_xor_sync(0xffffffffu, a11, ofs));
        a20 = add2(a20, __shfl_xor_sync(0xffffffffu, a20, ofs));
        a21 = add2(a21, __shfl_xor_sync(0xffffffffu, a21, ofs));
        a30 = add2(a30, __shfl_xor_sync(0xffffffffu, a30, ofs));
        a31 = add2(a31, __shfl_xor_sync(0xffffffffu, a31, ofs));
    }

    if (kl == 0) {
        float* dst = part + ((long)sk*512 + l0)*BB + h*4;
        float2 v;
        v=upk2(a00); dst[0]=v.x; dst[1]=v.y; v=upk2(a01); dst[2]=v.x; dst[3]=v.y;
        dst += BB;
        v=upk2(a10); dst[0]=v.x; dst[1]=v.y; v=upk2(a11); dst[2]=v.x; dst[3]=v.y;
        dst += BB;
        v=upk2(a20); dst[0]=v.x; dst[1]=v.y; v=upk2(a21); dst[2]=v.x; dst[3]=v.y;
        dst += BB;
        v=upk2(a30); dst[0]=v.x; dst[1]=v.y; v=upk2(a31); dst[2]=v.x; dst[3]=v.y;
    }
}

__global__ void __launch_bounds__(256) k_reduce(
    const float* __restrict__ part, const float* __restrict__ bm,
    const float* __restrict__ bs, float* __restrict__ out)
{
    int idx = blockIdx.x*256 + threadIdx.x;   // 4096
    int l = idx >> 3, b = idx & 7;
    float acc = (l < LATENT) ? bm[l] : bs[l - LATENT];
    for (int sk = 0; sk < SPLITD; sk++) acc += part[((long)sk*512 + l)*BB + b];
    out[b*512 + l] = acc;
}

// ---------------- launch ----------------
extern "C" void kernel_launch(void* const* d_in, const int* in_sizes, int n_in,
                              void* d_out, int out_size)
{
    const float* x      = (const float*)d_in[0];
    const int*   nb0    = (const int*)  d_in[1];
    const int*   nb1    = (const int*)  d_in[2];
    const int*   nb2    = (const int*)  d_in[3];
    const int*   nb3    = (const int*)  d_in[4];
    const float* w0     = (const float*)d_in[5];
    const float* bias0  = (const float*)d_in[6];
    const float* ww0    = (const float*)d_in[7];
    const float* pnb1   = (const float*)d_in[8];
    const float* w2     = (const float*)d_in[9];
    const float* bias2  = (const float*)d_in[10];
    const float* ww2    = (const float*)d_in[11];
    const float* pnb3   = (const float*)d_in[12];
    const float* Wm     = (const float*)d_in[13];
    const float* bm     = (const float*)d_in[14];
    const float* Ws     = (const float*)d_in[15];
    const float* bs     = (const float*)d_in[16];
    float* out = (float*)d_out;

    float *h1, *h2, *h3, *ft, *Bt, *part;
    cudaGetSymbolAddress((void**)&h1,   g_h1);
    cudaGetSymbolAddress((void**)&h2,   g_h2);
    cudaGetSymbolAddress((void**)&h3,   g_h3);
    cudaGetSymbolAddress((void**)&ft,   g_ft);
    cudaGetSymbolAddress((void**)&Bt,   g_Bt);
    cudaGetSymbolAddress((void**)&part, g_part);

    cudaFuncSetAttribute(k_conv2, cudaFuncAttributeMaxDynamicSharedMemorySize,
                         CONV2_SMEM);
    cudaFuncSetAttribute(k_dense, cudaFuncAttributeMaxDynamicSharedMemorySize,
                         DKS*BB*4);

    k_tw2   <<<KA3, C2>>>(w2, Bt);
    k_conv0 <<<P0/4, 256>>>(x, nb0, w0, bias0, ww0, h1);
    k_pool1 <<<P1, 128>>>(h1, nb1, pnb1, h2);
    k_conv2 <<<NROWS/GBM, 256, CONV2_SMEM>>>(h2, nb2, ww2, Bt, bias2, h3);
    k_pool3 <<<P2, 128>>>(h3, nb3, pnb3, ft);
    k_dense <<<16*SPLITD, 256, DKS*BB*4>>>(Wm, Ws, ft, part);
    k_reduce<<<16, 256>>>(part, bm, bs, out);
}

// round 7
// speedup vs baseline: 1.3977x; 1.0343x over previous
#include <cuda_runtime.h>
#include <cuda_bf16.h>

// Shapes
#define BB 8
#define P0 20000
#define P1 5000
#define P2 1250
#define MM 10
#define WW 9
#define C0 3
#define C1 64
#define C2 128
#define LATENT 256
#define FDIM (P2*C2)      // 160000
#define KA3 (WW*C1)       // 576
#define NROWS (BB*P1)     // 40000

typedef unsigned long long ull;

// ---------------- scratch (device globals; no allocation) ----------------
__device__ float g_h1[BB*P0*C1];        // 10.24M
__device__ float g_h2[BB*P1*C1];        // 2.56M
__device__ float g_s2[NROWS*KA3];       // 23.04M floats (92MB)
__device__ float g_h3[BB*P1*C2];        // 5.12M
__device__ float g_ft[FDIM*BB];         // 1.28M  (f transposed: [k][b])
__device__ float g_Bt[KA3*C2];          // 73728
#define SPLITD 100
#define DKS    1600                      // FDIM / SPLITD
__device__ float g_part[SPLITD*512*BB];  // 409600

__device__ __forceinline__ float eluf(float x){
    return x > 0.f ? x : (expf(x) - 1.f);
}

// ---------------- packed f32x2 helpers ----------------
__device__ __forceinline__ ull pk2(float lo, float hi){
    ull r;
    asm("mov.b64 %0, {%1,%2};" : "=l"(r) : "f"(lo), "f"(hi));
    return r;
}
__device__ __forceinline__ void fma2(ull &d, ull a, ull b){
    asm("fma.rn.f32x2 %0, %1, %2, %0;" : "+l"(d) : "l"(a), "l"(b));
}
__device__ __forceinline__ ull add2(ull a, ull b){
    ull r;
    asm("add.rn.f32x2 %0, %1, %2;" : "=l"(r) : "l"(a), "l"(b));
    return r;
}
__device__ __forceinline__ float2 upk2(ull v){
    float2 f;
    asm("mov.b64 {%0,%1}, %2;" : "=f"(f.x), "=f"(f.y) : "l"(v));
    return f;
}

// ---------------- stage 1: full_conv0 + elu ----------------
__global__ void __launch_bounds__(256) k_conv0(
    const float* __restrict__ x, const int* __restrict__ nb0,
    const float* __restrict__ w0, const float* __restrict__ bias0,
    const float* __restrict__ ww0, float* __restrict__ h1)
{
    const int PTS = 4;
    __shared__ float sw0[WW*C1*C0];            // 1728
    __shared__ float nbh[PTS][BB][MM][C0];     // 960
    __shared__ float w2s[PTS][MM][WW];         // 360
    __shared__ float ssh[PTS][BB][28];         // padded 27->28
    __shared__ int   nbs[PTS][MM];

    const int tid = threadIdx.x;
    const int p0 = blockIdx.x * PTS;

    for (int i = tid; i < WW*C1*C0; i += 256) sw0[i] = w0[i];

    if (tid < PTS*MM) {
        int pt = tid / MM, m = tid % MM;
        int nb = nb0[(p0+pt)*MM + m];
        bool valid = (nb != P0);
        nbs[pt][m] = valid ? nb : 0;
        const float* wp = ww0 + ((long)(p0+pt)*MM + m)*WW;
        #pragma unroll
        for (int w = 0; w < WW; w++) w2s[pt][m][w] = valid ? wp[w] : 0.f;
    }
    __syncthreads();

    for (int idx = tid; idx < PTS*BB*MM; idx += 256) {
        int pt = idx / (BB*MM); int rem = idx % (BB*MM);
        int b = rem / MM, m = rem % MM;
        const float* xr = x + ((long)b*P0 + nbs[pt][m]) * C0;
        nbh[pt][b][m][0] = xr[0];
        nbh[pt][b][m][1] = xr[1];
        nbh[pt][b][m][2] = xr[2];
    }
    __syncthreads();

    for (int idx = tid; idx < PTS*BB*27; idx += 256) {
        int pt = idx / (BB*27); int rem = idx % (BB*27);
        int b = rem / 27, k = rem % 27;
        int w = k / 3, i = k % 3;
        float acc = 0.f;
        #pragma unroll
        for (int m = 0; m < MM; m++) acc += w2s[pt][m][w] * nbh[pt][b][m][i];
        ssh[pt][b][k] = acc;
    }
    __syncthreads();

    const int o = tid & 63;
    float wr[27];
    #pragma unroll
    for (int k = 0; k < 27; k++) {
        int w = k / 3, i = k % 3;
        wr[k] = sw0[w*(C1*C0) + o*3 + i];
    }
    const float bv = bias0[o];
    const int pairbase = tid >> 6; // 0..3
    #pragma unroll
    for (int j = 0; j < 8; j++) {
        int pair = pairbase + j*4;     // 0..31
        int pt = pair >> 3, b = pair & 7;
        float acc = bv;
        #pragma unroll
        for (int k = 0; k < 27; k++) acc += wr[k] * ssh[pt][b][k];
        h1[((long)b*P0 + p0 + pt)*C1 + o] = eluf(acc);
    }
}

// ---------------- stage 2: pool1 + elu ----------------
__global__ void __launch_bounds__(128) k_pool1(
    const float* __restrict__ h1, const int* __restrict__ nb1,
    const float* __restrict__ pnb, float* __restrict__ h2)
{
    __shared__ float pn[MM];
    __shared__ int nbs[MM];
    const int p = blockIdx.x, tid = threadIdx.x;
    if (tid < MM) {
        int nb = nb1[p*MM + tid];
        bool valid = (nb != P0);
        nbs[tid] = valid ? nb : 0;
        pn[tid]  = valid ? fabsf(pnb[p*MM + tid]) : 0.f;
    }
    __syncthreads();
    float den = 1e-8f;
    #pragma unroll
    for (int m = 0; m < MM; m++) den += pn[m];
    const float inv = 1.f / den;

    for (int idx = tid; idx < BB*C1; idx += 128) {
        int b = idx >> 6, c = idx & 63;
        float acc = 0.f;
        #pragma unroll
        for (int m = 0; m < MM; m++)
            acc += pn[m] * h1[((long)b*P0 + nbs[m])*C1 + c];
        h2[((long)b*P1 + p)*C1 + c] = eluf(acc * inv);
    }
}

// ---------------- stage 3a: s2[b*P1+p][w*64+i] ----------------
__global__ void __launch_bounds__(256) k_s2(
    const float* __restrict__ h2, const int* __restrict__ nb2,
    const float* __restrict__ ww2, float* __restrict__ s2)
{
    __shared__ float nbh[BB][MM][C1];  // 20KB
    __shared__ float w2s[MM][WW];
    __shared__ int nbs[MM];
    const int p = blockIdx.x, tid = threadIdx.x;
    if (tid < MM) {
        int nb = nb2[p*MM + tid];
        nbs[tid] = (nb != P1) ? nb : -1;
    }
    __syncthreads();
    if (tid < MM*WW) {
        int m = tid / WW, w = tid % WW;
        w2s[m][w] = (nbs[m] >= 0) ? ww2[((long)p*MM + m)*WW + w] : 0.f;
    }
    for (int idx = tid; idx < BB*MM*C1; idx += 256) {
        int b = idx / (MM*C1); int rem = idx % (MM*C1);
        int m = rem / C1, i = rem & 63;
        int nb = nbs[m];
        nbh[b][m][i] = (nb >= 0) ? h2[((long)b*P1 + nb)*C1 + i] : 0.f;
    }
    __syncthreads();
    for (int idx = tid; idx < BB*KA3; idx += 256) {
        int b = idx / KA3, k = idx % KA3;
        int w = k >> 6, i = k & 63;
        float acc = 0.f;
        #pragma unroll
        for (int m = 0; m < MM; m++) acc += w2s[m][w] * nbh[b][m][i];
        s2[(long)(b*P1 + p)*KA3 + k] = acc;
    }
}

// ---------------- weights2 transpose: Bt[(w*64+i)*128 + o] ----------------
__global__ void k_tw2(const float* __restrict__ w2g, float* __restrict__ Bt){
    int k = blockIdx.x;   // 576
    int o = threadIdx.x;  // 128
    int w = k >> 6, i = k & 63;
    Bt[k*C2 + o] = w2g[w*(C2*C1) + o*C1 + i];
}

// ---------------- stage 3b: double-buffered SGEMM 40000x128x576 + bias + elu ----------------
#define TBM 64
#define TBN 128
#define TBK 16
__global__ void __launch_bounds__(256, 3) k_gemm(
    const float* __restrict__ A, const float* __restrict__ Bt,
    const float* __restrict__ bias, float* __restrict__ C)
{
    __shared__ float As[2][TBK][68];     // [k][row], padded
    __shared__ float Bs[2][TBK][TBN];    // [k][col]
    const int tid = threadIdx.x;
    const long r0 = (long)blockIdx.x * TBM;

    const int lar = tid >> 2;          // 0..63
    const int lak = (tid & 3) << 2;    // 0,4,8,12
    const int lbk = tid >> 5;          // 0..7
    const int lbn = (tid & 31) << 2;   // 0..124

    const int trow = (tid >> 4) << 2;  // 0..60
    const int tcol = (tid & 15) << 3;  // 0..120

    const float* Aptr  = A  + (r0 + lar)*KA3 + lak;
    const float* Bptr0 = Bt + lbk*TBN + lbn;
    const float* Bptr1 = Bt + (lbk + 8)*TBN + lbn;

    // prologue: stage 0
    {
        float4 av  = *(const float4*)(Aptr);
        float4 bv0 = *(const float4*)(Bptr0);
        float4 bv1 = *(const float4*)(Bptr1);
        As[0][lak+0][lar] = av.x;
        As[0][lak+1][lar] = av.y;
        As[0][lak+2][lar] = av.z;
        As[0][lak+3][lar] = av.w;
        *(float4*)&Bs[0][lbk  ][lbn] = bv0;
        *(float4*)&Bs[0][lbk+8][lbn] = bv1;
    }
    __syncthreads();

    ull acc[16];
    #pragma unroll
    for (int i = 0; i < 16; i++) acc[i] = 0ULL;

    int buf = 0;
    for (int kt = 0; kt < KA3; kt += TBK) {
        const bool more = (kt + TBK) < KA3;
        float4 avn, bv0n, bv1n;
        if (more) {
            avn  = *(const float4*)(Aptr  + kt + TBK);
            bv0n = *(const float4*)(Bptr0 + (long)(kt + TBK)*TBN);
            bv1n = *(const float4*)(Bptr1 + (long)(kt + TBK)*TBN);
        }
        #pragma unroll
        for (int kk = 0; kk < TBK; kk++) {
            float4 a  = *(const float4*)&As[buf][kk][trow];
            float4 b0 = *(const float4*)&Bs[buf][kk][tcol];
            float4 b1 = *(const float4*)&Bs[buf][kk][tcol + 4];
            ull pb0 = pk2(b0.x, b0.y);
            ull pb1 = pk2(b0.z, b0.w);
            ull pb2 = pk2(b1.x, b1.y);
            ull pb3 = pk2(b1.z, b1.w);
            ull pa0 = pk2(a.x, a.x);
            ull pa1 = pk2(a.y, a.y);
            ull pa2 = pk2(a.z, a.z);
            ull pa3 = pk2(a.w, a.w);
            fma2(acc[ 0], pa0, pb0); fma2(acc[ 1], pa0, pb1);
            fma2(acc[ 2], pa0, pb2); fma2(acc[ 3], pa0, pb3);
            fma2(acc[ 4], pa1, pb0); fma2(acc[ 5], pa1, pb1);
            fma2(acc[ 6], pa1, pb2); fma2(acc[ 7], pa1, pb3);
            fma2(acc[ 8], pa2, pb0); fma2(acc[ 9], pa2, pb1);
            fma2(acc[10], pa2, pb2); fma2(acc[11], pa2, pb3);
            fma2(acc[12], pa3, pb0); fma2(acc[13], pa3, pb1);
            fma2(acc[14], pa3, pb2); fma2(acc[15], pa3, pb3);
        }
        if (more) {
            As[buf^1][lak+0][lar] = avn.x;
            As[buf^1][lak+1][lar] = avn.y;
            As[buf^1][lak+2][lar] = avn.z;
            As[buf^1][lak+3][lar] = avn.w;
            *(float4*)&Bs[buf^1][lbk  ][lbn] = bv0n;
            *(float4*)&Bs[buf^1][lbk+8][lbn] = bv1n;
        }
        __syncthreads();
        buf ^= 1;
    }

    // epilogue: bias + elu
    float4 bia0 = *(const float4*)(bias + tcol);
    float4 bia1 = *(const float4*)(bias + tcol + 4);
    #pragma unroll
    for (int i = 0; i < 4; i++) {
        long r = r0 + trow + i;
        float2 v0 = upk2(acc[i*4 + 0]);
        float2 v1 = upk2(acc[i*4 + 1]);
        float2 v2 = upk2(acc[i*4 + 2]);
        float2 v3 = upk2(acc[i*4 + 3]);
        float4 o0, o1;
        o0.x = eluf(v0.x + bia0.x); o0.y = eluf(v0.y + bia0.y);
        o0.z = eluf(v1.x + bia0.z); o0.w = eluf(v1.y + bia0.w);
        o1.x = eluf(v2.x + bia1.x); o1.y = eluf(v2.y + bia1.y);
        o1.z = eluf(v3.x + bia1.z); o1.w = eluf(v3.y + bia1.w);
        *(float4*)&C[r*TBN + tcol    ] = o0;
        *(float4*)&C[r*TBN + tcol + 4] = o1;
    }
}

// ---------------- stage 4: pool3 + elu, writes f TRANSPOSED ft[k][b] ----------------
__global__ void __launch_bounds__(128) k_pool3(
    const float* __restrict__ h3, const int* __restrict__ nb3,
    const float* __restrict__ pnb, float* __restrict__ ft)
{
    __shared__ float pn[MM];
    __shared__ int nbs[MM];
    const int p = blockIdx.x, tid = threadIdx.x;
    if (tid < MM) {
        int nb = nb3[p*MM + tid];
        bool valid = (nb != P1);
        nbs[tid] = valid ? nb : 0;
        pn[tid]  = valid ? fabsf(pnb[p*MM + tid]) : 0.f;
    }
    __syncthreads();
    float den = 1e-8f;
    #pragma unroll
    for (int m = 0; m < MM; m++) den += pn[m];
    const float inv = 1.f / den;
    const int c = tid; // 128
    float out[BB];
    #pragma unroll
    for (int b = 0; b < BB; b++) {
        float acc = 0.f;
        #pragma unroll
        for (int m = 0; m < MM; m++)
            acc += pn[m] * h3[((long)b*P1 + nbs[m])*C2 + c];
        out[b] = eluf(acc * inv);
    }
    float4* d = (float4*)(ft + ((long)p*C2 + c)*BB);
    d[0] = make_float4(out[0], out[1], out[2], out[3]);
    d[1] = make_float4(out[4], out[5], out[6], out[7]);
}

// ---------------- stage 5: dense head ----------------
// ft[k][b]; warp handles 4 W rows; lane = (kl 0..15, b-half).
// Butterfly reduction over kl (lane bits 1..4) before the write.
__global__ void __launch_bounds__(256) k_dense(
    const float* __restrict__ Wm, const float* __restrict__ Ws,
    const float* __restrict__ ft, float* __restrict__ part)
{
    extern __shared__ float fs[];   // DKS*8 floats
    const int tid = threadIdx.x;
    const int rb = blockIdx.x & 15;      // 0..15  (32 rows each)
    const int sk = blockIdx.x >> 4;      // 0..SPLITD-1
    const int kbase = sk * DKS;

    {
        const float4* src = (const float4*)(ft + (long)kbase*BB);
        float4* dst = (float4*)fs;
        for (int i = tid; i < DKS*BB/4; i += 256) dst[i] = src[i];
    }
    __syncthreads();

    const int warp = tid >> 5, lane = tid & 31;
    const int l0 = rb*32 + warp*4;
    const float* Wb = (l0 < LATENT) ? (Wm + (long)l0*FDIM)
                                    : (Ws + (long)(l0 - LATENT)*FDIM);
    const float* W0 = Wb;
    const float* W1 = Wb + FDIM;
    const float* W2p = Wb + 2L*FDIM;
    const float* W3 = Wb + 3L*FDIM;

    const int kl = lane >> 1;      // 0..15
    const int h  = lane & 1;       // b-half
    const float* fpb = fs + h*4;

    ull a00=0,a01=0,a10=0,a11=0,a20=0,a21=0,a30=0,a31=0;

    #pragma unroll 2
    for (int t = 0; t < DKS/16; t++) {
        int k = t*16 + kl;
        float4 fv = *(const float4*)(fpb + k*8);
        ull f01 = pk2(fv.x, fv.y);
        ull f23 = pk2(fv.z, fv.w);
        long kg = kbase + k;
        float w0 = W0[kg], w1 = W1[kg], w2v = W2p[kg], w3 = W3[kg];
        ull p0 = pk2(w0,w0), p1 = pk2(w1,w1), p2 = pk2(w2v,w2v), p3 = pk2(w3,w3);
        fma2(a00,p0,f01); fma2(a01,p0,f23);
        fma2(a10,p1,f01); fma2(a11,p1,f23);
        fma2(a20,p2,f01); fma2(a21,p2,f23);
        fma2(a30,p3,f01); fma2(a31,p3,f23);
    }

    #pragma unroll
    for (int ofs = 2; ofs < 32; ofs <<= 1) {
        a00 = add2(a00, __shfl_xor_sync(0xffffffffu, a00, ofs));
        a01 = add2(a01, __shfl_xor_sync(0xffffffffu, a01, ofs));
        a10 = add2(a10, __shfl_xor_sync(0xffffffffu, a10, ofs));
        a11 = add2(a11, __shfl_xor_sync(0xffffffffu, a11, ofs));
        a20 = add2(a20, __shfl_xor_sync(0xffffffffu, a20, ofs));
        a21 = add2(a21, __shfl_xor_sync(0xffffffffu, a21, ofs));
        a30 = add2(a30, __shfl_xor_sync(0xffffffffu, a30, ofs));
        a31 = add2(a31, __shfl_xor_sync(0xffffffffu, a31, ofs));
    }

    if (kl == 0) {
        float* dst = part + ((long)sk*512 + l0)*BB + h*4;
        float2 v;
        v=upk2(a00); dst[0]=v.x; dst[1]=v.y; v=upk2(a01); dst[2]=v.x; dst[3]=v.y;
        dst += BB;
        v=upk2(a10); dst[0]=v.x; dst[1]=v.y; v=upk2(a11); dst[2]=v.x; dst[3]=v.y;
        dst += BB;
        v=upk2(a20); dst[0]=v.x; dst[1]=v.y; v=upk2(a21); dst[2]=v.x; dst[3]=v.y;
        dst += BB;
        v=upk2(a30); dst[0]=v.x; dst[1]=v.y; v=upk2(a31); dst[2]=v.x; dst[3]=v.y;
    }
}

__global__ void __launch_bounds__(256) k_reduce(
    const float* __restrict__ part, const float* __restrict__ bm,
    const float* __restrict__ bs, float* __restrict__ out)
{
    int idx = blockIdx.x*256 + threadIdx.x;   // 4096
    int l = idx >> 3, b = idx & 7;
    float acc = (l < LATENT) ? bm[l] : bs[l - LATENT];
    for (int sk = 0; sk < SPLITD; sk++) acc += part[((long)sk*512 + l)*BB + b];
    out[b*512 + l] = acc;
}

// ---------------- launch ----------------
extern "C" void kernel_launch(void* const* d_in, const int* in_sizes, int n_in,
                              void* d_out, int out_size)
{
    const float* x      = (const float*)d_in[0];
    const int*   nb0    = (const int*)  d_in[1];
    const int*   nb1    = (const int*)  d_in[2];
    const int*   nb2    = (const int*)  d_in[3];
    const int*   nb3    = (const int*)  d_in[4];
    const float* w0     = (const float*)d_in[5];
    const float* bias0  = (const float*)d_in[6];
    const float* ww0    = (const float*)d_in[7];
    const float* pnb1   = (const float*)d_in[8];
    const float* w2     = (const float*)d_in[9];
    const float* bias2  = (const float*)d_in[10];
    const float* ww2    = (const float*)d_in[11];
    const float* pnb3   = (const float*)d_in[12];
    const float* Wm     = (const float*)d_in[13];
    const float* bm     = (const float*)d_in[14];
    const float* Ws     = (const float*)d_in[15];
    const float* bs     = (const float*)d_in[16];
    float* out = (float*)d_out;

    float *h1, *h2, *s2, *h3, *ft, *Bt, *part;
    cudaGetSymbolAddress((void**)&h1,   g_h1);
    cudaGetSymbolAddress((void**)&h2,   g_h2);
    cudaGetSymbolAddress((void**)&s2,   g_s2);
    cudaGetSymbolAddress((void**)&h3,   g_h3);
    cudaGetSymbolAddress((void**)&ft,   g_ft);
    cudaGetSymbolAddress((void**)&Bt,   g_Bt);
    cudaGetSymbolAddress((void**)&part, g_part);

    cudaFuncSetAttribute(k_dense, cudaFuncAttributeMaxDynamicSharedMemorySize,
                         DKS*BB*4);

    k_tw2   <<<KA3, C2>>>(w2, Bt);
    k_conv0 <<<P0/4, 256>>>(x, nb0, w0, bias0, ww0, h1);
    k_pool1 <<<P1, 128>>>(h1, nb1, pnb1, h2);
    k_s2    <<<P1, 256>>>(h2, nb2, ww2, s2);
    k_gemm  <<<NROWS/TBM, 256>>>(s2, Bt, bias2, h3);
    k_pool3 <<<P2, 128>>>(h3, nb3, pnb3, ft);
    k_dense <<<16*SPLITD, 256, DKS*BB*4>>>(Wm, Ws, ft, part);
    k_reduce<<<16, 256>>>(part, bm, bs, out);
}

// round 11
// speedup vs baseline: 1.6233x; 1.1614x over previous
#include <cuda_runtime.h>
#include <cuda_bf16.h>

// Shapes
#define BB 8
#define P0 20000
#define P1 5000
#define P2 1250
#define MM 10
#define WW 9
#define C0 3
#define C1 64
#define C2 128
#define LATENT 256
#define FDIM (P2*C2)      // 160000
#define KA3 (WW*C1)       // 576
#define NROWS (BB*P1)     // 40000
#define GBM 128
#define NBLK 313          // ceil(40000/128)
#define AROWS (NBLK*GBM)  // 40064 (padded rows; tail garbage, stores guarded)

typedef unsigned long long ull;

// ---------------- scratch (device globals; no allocation) ----------------
__device__ float g_h1[BB*P0*C1];        // 10.24M
__device__ float g_h2[BB*P1*C1];        // 2.56M
__device__ float g_s2[(long)AROWS*KA3]; // 23.08M floats
__device__ float g_h3[BB*P1*C2];        // 5.12M
__device__ float g_ft[FDIM*BB];         // 1.28M  (f transposed: [k][b])
__device__ float g_Bt[KA3*C2];          // 73728
#define SPLITD 100
#define DKS    1600                      // FDIM / SPLITD
__device__ float g_part[SPLITD*512*BB];  // 409600

__device__ __forceinline__ float eluf(float x){
    return x > 0.f ? x : (expf(x) - 1.f);
}

// ---------------- packed f32x2 helpers ----------------
__device__ __forceinline__ ull pk2(float lo, float hi){
    ull r; asm("mov.b64 %0, {%1,%2};" : "=l"(r) : "f"(lo), "f"(hi)); return r;
}
__device__ __forceinline__ void fma2(ull &d, ull a, ull b){
    asm("fma.rn.f32x2 %0, %1, %2, %0;" : "+l"(d) : "l"(a), "l"(b));
}
__device__ __forceinline__ ull add2(ull a, ull b){
    ull r; asm("add.rn.f32x2 %0, %1, %2;" : "=l"(r) : "l"(a), "l"(b)); return r;
}
__device__ __forceinline__ float2 upk2(ull v){
    float2 f; asm("mov.b64 {%0,%1}, %2;" : "=f"(f.x), "=f"(f.y) : "l"(v)); return f;
}

// ---------------- stage 1: full_conv0 + elu ----------------
__global__ void __launch_bounds__(256) k_conv0(
    const float* __restrict__ x, const int* __restrict__ nb0,
    const float* __restrict__ w0, const float* __restrict__ bias0,
    const float* __restrict__ ww0, float* __restrict__ h1)
{
    const int PTS = 4;
    __shared__ float sw0[WW*C1*C0];
    __shared__ float nbh[PTS][BB][MM][C0];
    __shared__ float w2s[PTS][MM][WW];
    __shared__ float ssh[PTS][BB][28];
    __shared__ int   nbs[PTS][MM];

    const int tid = threadIdx.x;
    const int p0 = blockIdx.x * PTS;

    for (int i = tid; i < WW*C1*C0; i += 256) sw0[i] = w0[i];

    if (tid < PTS*MM) {
        int pt = tid / MM, m = tid % MM;
        int nb = nb0[(p0+pt)*MM + m];
        bool valid = (nb != P0);
        nbs[pt][m] = valid ? nb : 0;
        const float* wp = ww0 + ((long)(p0+pt)*MM + m)*WW;
        #pragma unroll
        for (int w = 0; w < WW; w++) w2s[pt][m][w] = valid ? wp[w] : 0.f;
    }
    __syncthreads();

    for (int idx = tid; idx < PTS*BB*MM; idx += 256) {
        int pt = idx / (BB*MM); int rem = idx % (BB*MM);
        int b = rem / MM, m = rem % MM;
        const float* xr = x + ((long)b*P0 + nbs[pt][m]) * C0;
        nbh[pt][b][m][0] = xr[0];
        nbh[pt][b][m][1] = xr[1];
        nbh[pt][b][m][2] = xr[2];
    }
    __syncthreads();

    for (int idx = tid; idx < PTS*BB*27; idx += 256) {
        int pt = idx / (BB*27); int rem = idx % (BB*27);
        int b = rem / 27, k = rem % 27;
        int w = k / 3, i = k % 3;
        float acc = 0.f;
        #pragma unroll
        for (int m = 0; m < MM; m++) acc += w2s[pt][m][w] * nbh[pt][b][m][i];
        ssh[pt][b][k] = acc;
    }
    __syncthreads();

    const int o = tid & 63;
    float wr[27];
    #pragma unroll
    for (int k = 0; k < 27; k++) {
        int w = k / 3, i = k % 3;
        wr[k] = sw0[w*(C1*C0) + o*3 + i];
    }
    const float bv = bias0[o];
    const int pairbase = tid >> 6;
    #pragma unroll
    for (int j = 0; j < 8; j++) {
        int pair = pairbase + j*4;
        int pt = pair >> 3, b = pair & 7;
        float acc = bv;
        #pragma unroll
        for (int k = 0; k < 27; k++) acc += wr[k] * ssh[pt][b][k];
        h1[((long)b*P0 + p0 + pt)*C1 + o] = eluf(acc);
    }
}

// ---------------- stage 2: pool1 + elu ----------------
__global__ void __launch_bounds__(128) k_pool1(
    const float* __restrict__ h1, const int* __restrict__ nb1,
    const float* __restrict__ pnb, float* __restrict__ h2)
{
    __shared__ float pn[MM];
    __shared__ int nbs[MM];
    const int p = blockIdx.x, tid = threadIdx.x;
    if (tid < MM) {
        int nb = nb1[p*MM + tid];
        bool valid = (nb != P0);
        nbs[tid] = valid ? nb : 0;
        pn[tid]  = valid ? fabsf(pnb[p*MM + tid]) : 0.f;
    }
    __syncthreads();
    float den = 1e-8f;
    #pragma unroll
    for (int m = 0; m < MM; m++) den += pn[m];
    const float inv = 1.f / den;

    for (int idx = tid; idx < BB*C1; idx += 128) {
        int b = idx >> 6, c = idx & 63;
        float acc = 0.f;
        #pragma unroll
        for (int m = 0; m < MM; m++)
            acc += pn[m] * h1[((long)b*P0 + nbs[m])*C1 + c];
        h2[((long)b*P1 + p)*C1 + c] = eluf(acc * inv);
    }
}

// ---------------- stage 3a: s2[b*P1+p][w*64+i], f32x2 tap accumulation ----------------
__global__ void __launch_bounds__(256) k_s2(
    const float* __restrict__ h2, const int* __restrict__ nb2,
    const float* __restrict__ ww2, float* __restrict__ s2)
{
    __shared__ float nbh[BB][MM][C1];  // 20KB
    __shared__ float w2s[MM][WW];
    __shared__ int nbs[MM];
    const int p = blockIdx.x, tid = threadIdx.x;
    if (tid < MM) {
        int nb = nb2[p*MM + tid];
        nbs[tid] = (nb != P1) ? nb : -1;
    }
    __syncthreads();
    if (tid < MM*WW) {
        int m = tid / WW, w = tid % WW;
        w2s[m][w] = (nbs[m] >= 0) ? ww2[((long)p*MM + m)*WW + w] : 0.f;
    }
    for (int idx = tid; idx < BB*MM*C1; idx += 256) {
        int b = idx / (MM*C1); int rem = idx % (MM*C1);
        int m = rem / C1, i = rem & 63;
        int nb = nbs[m];
        nbh[b][m][i] = (nb >= 0) ? h2[((long)b*P1 + nb)*C1 + i] : 0.f;
    }
    __syncthreads();
    // one f32x2 pair per element-pair: BB*KA3/2 = 2304 pairs, 9 per thread
    for (int idx = tid; idx < BB*(KA3/2); idx += 256) {
        int b  = idx / (KA3/2);
        int k2 = idx - b*(KA3/2);        // 0..287
        int w  = k2 >> 5;                // 0..8
        int i  = (k2 & 31) << 1;         // even 0..62
        const float* nbb = &nbh[b][0][i];
        ull acc = 0ULL;
        #pragma unroll
        for (int m = 0; m < MM; m++) {
            float wv = w2s[m][w];
            fma2(acc, pk2(wv, wv), *(const ull*)(nbb + m*C1));
        }
        *(ull*)&s2[(long)(b*P1 + p)*KA3 + (k2 << 1)] = acc;
    }
}

// ---------------- weights2 transpose: Bt[(w*64+i)*128 + o] ----------------
__global__ void k_tw2(const float* __restrict__ w2g, float* __restrict__ Bt){
    int k = blockIdx.x;   // 576
    int o = threadIdx.x;  // 128
    int w = k >> 6, i = k & 63;
    Bt[k*C2 + o] = w2g[w*(C2*C1) + o*C1 + i];
}

// ---------------- stage 3b: 128x128x8 double-buffered SGEMM + bias + elu ----------------
#define TBN 128
#define TBK 8
__global__ void __launch_bounds__(256, 2) k_gemm(
    const float* __restrict__ A, const float* __restrict__ Bt,
    const float* __restrict__ bias, float* __restrict__ C)
{
    __shared__ float As[2][TBK][GBM + 4];   // [k][row], padded
    __shared__ float Bs[2][TBK][TBN];       // [k][col]
    const int tid = threadIdx.x;
    const long r0 = (long)blockIdx.x * GBM;

    const int lar = tid >> 1;          // 0..127
    const int lak = (tid & 1) << 2;    // 0,4
    const int lbk = tid >> 5;          // 0..7
    const int lbn = (tid & 31) << 2;   // 0..124

    const int ty = tid >> 4;           // 0..15 -> rows ty*8..+7
    const int tx = tid & 15;           // 0..15 -> cols tx*8..+7

    const float* Aptr = A  + (r0 + lar)*KA3 + lak;
    const float* Bptr = Bt + lbk*TBN + lbn;

    // prologue
    {
        float4 av = *(const float4*)(Aptr);
        float4 bv = *(const float4*)(Bptr);
        As[0][lak+0][lar] = av.x;
        As[0][lak+1][lar] = av.y;
        As[0][lak+2][lar] = av.z;
        As[0][lak+3][lar] = av.w;
        *(float4*)&Bs[0][lbk][lbn] = bv;
    }
    __syncthreads();

    ull acc[32];
    #pragma unroll
    for (int i = 0; i < 32; i++) acc[i] = 0ULL;

    int buf = 0;
    for (int kt = 0; kt < KA3; kt += TBK) {
        const bool more = (kt + TBK) < KA3;
        float4 avn, bvn;
        if (more) {
            avn = *(const float4*)(Aptr + kt + TBK);
            bvn = *(const float4*)(Bptr + (long)(kt + TBK)*TBN);
        }
        #pragma unroll
        for (int kk = 0; kk < TBK; kk++) {
            float4 a0 = *(const float4*)&As[buf][kk][ty*8];
            float4 a1 = *(const float4*)&As[buf][kk][ty*8 + 4];
            float4 b0 = *(const float4*)&Bs[buf][kk][tx*8];
            float4 b1 = *(const float4*)&Bs[buf][kk][tx*8 + 4];
            ull pb0 = pk2(b0.x, b0.y);
            ull pb1 = pk2(b0.z, b0.w);
            ull pb2 = pk2(b1.x, b1.y);
            ull pb3 = pk2(b1.z, b1.w);
            ull pa;
            pa = pk2(a0.x, a0.x);
            fma2(acc[ 0], pa, pb0); fma2(acc[ 1], pa, pb1);
            fma2(acc[ 2], pa, pb2); fma2(acc[ 3], pa, pb3);
            pa = pk2(a0.y, a0.y);
            fma2(acc[ 4], pa, pb0); fma2(acc[ 5], pa, pb1);
            fma2(acc[ 6], pa, pb2); fma2(acc[ 7], pa, pb3);
            pa = pk2(a0.z, a0.z);
            fma2(acc[ 8], pa, pb0); fma2(acc[ 9], pa, pb1);
            fma2(acc[10], pa, pb2); fma2(acc[11], pa, pb3);
            pa = pk2(a0.w, a0.w);
            fma2(acc[12], pa, pb0); fma2(acc[13], pa, pb1);
            fma2(acc[14], pa, pb2); fma2(acc[15], pa, pb3);
            pa = pk2(a1.x, a1.x);
            fma2(acc[16], pa, pb0); fma2(acc[17], pa, pb1);
            fma2(acc[18], pa, pb2); fma2(acc[19], pa, pb3);
            pa = pk2(a1.y, a1.y);
            fma2(acc[20], pa, pb0); fma2(acc[21], pa, pb1);
            fma2(acc[22], pa, pb2); fma2(acc[23], pa, pb3);
            pa = pk2(a1.z, a1.z);
            fma2(acc[24], pa, pb0); fma2(acc[25], pa, pb1);
            fma2(acc[26], pa, pb2); fma2(acc[27], pa, pb3);
            pa = pk2(a1.w, a1.w);
            fma2(acc[28], pa, pb0); fma2(acc[29], pa, pb1);
            fma2(acc[30], pa, pb2); fma2(acc[31], pa, pb3);
        }
        if (more) {
            As[buf^1][lak+0][lar] = avn.x;
            As[buf^1][lak+1][lar] = avn.y;
            As[buf^1][lak+2][lar] = avn.z;
            As[buf^1][lak+3][lar] = avn.w;
            *(float4*)&Bs[buf^1][lbk][lbn] = bvn;
        }
        __syncthreads();
        buf ^= 1;
    }

    // epilogue: bias + elu, store 8 rows x 8 cols (row-guarded)
    float4 bia0 = *(const float4*)(bias + tx*8);
    float4 bia1 = *(const float4*)(bias + tx*8 + 4);
    #pragma unroll
    for (int i = 0; i < 8; i++) {
        long r = r0 + ty*8 + i;
        if (r >= NROWS) break;
        float2 v0 = upk2(acc[i*4 + 0]);
        float2 v1 = upk2(acc[i*4 + 1]);
        float2 v2 = upk2(acc[i*4 + 2]);
        float2 v3 = upk2(acc[i*4 + 3]);
        float4 o0, o1;
        o0.x = eluf(v0.x + bia0.x); o0.y = eluf(v0.y + bia0.y);
        o0.z = eluf(v1.x + bia0.z); o0.w = eluf(v1.y + bia0.w);
        o1.x = eluf(v2.x + bia1.x); o1.y = eluf(v2.y + bia1.y);
        o1.z = eluf(v3.x + bia1.z); o1.w = eluf(v3.y + bia1.w);
        *(float4*)&C[r*TBN + tx*8    ] = o0;
        *(float4*)&C[r*TBN + tx*8 + 4] = o1;
    }
}

// ---------------- stage 4: pool3 + elu, writes f TRANSPOSED ft[k][b] ----------------
__global__ void __launch_bounds__(128) k_pool3(
    const float* __restrict__ h3, const int* __restrict__ nb3,
    const float* __restrict__ pnb, float* __restrict__ ft)
{
    __shared__ float pn[MM];
    __shared__ int nbs[MM];
    const int p = blockIdx.x, tid = threadIdx.x;
    if (tid < MM) {
        int nb = nb3[p*MM + tid];
        bool valid = (nb != P1);
        nbs[tid] = valid ? nb : 0;
        pn[tid]  = valid ? fabsf(pnb[p*MM + tid]) : 0.f;
    }
    __syncthreads();
    float den = 1e-8f;
    #pragma unroll
    for (int m = 0; m < MM; m++) den += pn[m];
    const float inv = 1.f / den;
    const int c = tid;
    float out[BB];
    #pragma unroll
    for (int b = 0; b < BB; b++) {
        float acc = 0.f;
        #pragma unroll
        for (int m = 0; m < MM; m++)
            acc += pn[m] * h3[((long)b*P1 + nbs[m])*C2 + c];
        out[b] = eluf(acc * inv);
    }
    float4* d = (float4*)(ft + ((long)p*C2 + c)*BB);
    d[0] = make_float4(out[0], out[1], out[2], out[3]);
    d[1] = make_float4(out[4], out[5], out[6], out[7]);
}

// ---------------- stage 5: dense head ----------------
__global__ void __launch_bounds__(256) k_dense(
    const float* __restrict__ Wm, const float* __restrict__ Ws,
    const float* __restrict__ ft, float* __restrict__ part)
{
    extern __shared__ float fs[];
    const int tid = threadIdx.x;
    const int rb = blockIdx.x & 15;
    const int sk = blockIdx.x >> 4;
    const int kbase = sk * DKS;

    {
        const float4* src = (const float4*)(ft + (long)kbase*BB);
        float4* dst = (float4*)fs;
        for (int i = tid; i < DKS*BB/4; i += 256) dst[i] = src[i];
    }
    __syncthreads();

    const int warp = tid >> 5, lane = tid & 31;
    const int l0 = rb*32 + warp*4;
    const float* Wb = (l0 < LATENT) ? (Wm + (long)l0*FDIM)
                                    : (Ws + (long)(l0 - LATENT)*FDIM);
    const float* W0 = Wb;
    const float* W1 = Wb + FDIM;
    const float* W2p = Wb + 2L*FDIM;
    const float* W3 = Wb + 3L*FDIM;

    const int kl = lane >> 1;
    const int h  = lane & 1;
    const float* fpb = fs + h*4;

    ull a00=0,a01=0,a10=0,a11=0,a20=0,a21=0,a30=0,a31=0;

    #pragma unroll 2
    for (int t = 0; t < DKS/16; t++) {
        int k = t*16 + kl;
        float4 fv = *(const float4*)(fpb + k*8);
        ull f01 = pk2(fv.x, fv.y);
        ull f23 = pk2(fv.z, fv.w);
        long kg = kbase + k;
        float w0 = W0[kg], w1 = W1[kg], w2v = W2p[kg], w3 = W3[kg];
        ull p0 = pk2(w0,w0), p1 = pk2(w1,w1), p2 = pk2(w2v,w2v), p3 = pk2(w3,w3);
        fma2(a00,p0,f01); fma2(a01,p0,f23);
        fma2(a10,p1,f01); fma2(a11,p1,f23);
        fma2(a20,p2,f01); fma2(a21,p2,f23);
        fma2(a30,p3,f01); fma2(a31,p3,f23);
    }

    #pragma unroll
    for (int ofs = 2; ofs < 32; ofs <<= 1) {
        a00 = add2(a00, __shfl_xor_sync(0xffffffffu, a00, ofs));
        a01 = add2(a01, __shfl_xor_sync(0xffffffffu, a01, ofs));
        a10 = add2(a10, __shfl_xor_sync(0xffffffffu, a10, ofs));
        a11 = add2(a11, __shfl_xor_sync(0xffffffffu, a11, ofs));
        a20 = add2(a20, __shfl_xor_sync(0xffffffffu, a20, ofs));
        a21 = add2(a21, __shfl_xor_sync(0xffffffffu, a21, ofs));
        a30 = add2(a30, __shfl_xor_sync(0xffffffffu, a30, ofs));
        a31 = add2(a31, __shfl_xor_sync(0xffffffffu, a31, ofs));
    }

    if (kl == 0) {
        float* dst = part + ((long)sk*512 + l0)*BB + h*4;
        float2 v;
        v=upk2(a00); dst[0]=v.x; dst[1]=v.y; v=upk2(a01); dst[2]=v.x; dst[3]=v.y;
        dst += BB;
        v=upk2(a10); dst[0]=v.x; dst[1]=v.y; v=upk2(a11); dst[2]=v.x; dst[3]=v.y;
        dst += BB;
        v=upk2(a20); dst[0]=v.x; dst[1]=v.y; v=upk2(a21); dst[2]=v.x; dst[3]=v.y;
        dst += BB;
        v=upk2(a30); dst[0]=v.x; dst[1]=v.y; v=upk2(a31); dst[2]=v.x; dst[3]=v.y;
    }
}

__global__ void __launch_bounds__(256) k_reduce(
    const float* __restrict__ part, const float* __restrict__ bm,
    const float* __restrict__ bs, float* __restrict__ out)
{
    int idx = blockIdx.x*256 + threadIdx.x;
    int l = idx >> 3, b = idx & 7;
    float acc = (l < LATENT) ? bm[l] : bs[l - LATENT];
    for (int sk = 0; sk < SPLITD; sk++) acc += part[((long)sk*512 + l)*BB + b];
    out[b*512 + l] = acc;
}

// ---------------- launch ----------------
extern "C" void kernel_launch(void* const* d_in, const int* in_sizes, int n_in,
                              void* d_out, int out_size)
{
    const float* x      = (const float*)d_in[0];
    const int*   nb0    = (const int*)  d_in[1];
    const int*   nb1    = (const int*)  d_in[2];
    const int*   nb2    = (const int*)  d_in[3];
    const int*   nb3    = (const int*)  d_in[4];
    const float* w0     = (const float*)d_in[5];
    const float* bias0  = (const float*)d_in[6];
    const float* ww0    = (const float*)d_in[7];
    const float* pnb1   = (const float*)d_in[8];
    const float* w2     = (const float*)d_in[9];
    const float* bias2  = (const float*)d_in[10];
    const float* ww2    = (const float*)d_in[11];
    const float* pnb3   = (const float*)d_in[12];
    const float* Wm     = (const float*)d_in[13];
    const float* bm     = (const float*)d_in[14];
    const float* Ws     = (const float*)d_in[15];
    const float* bs     = (const float*)d_in[16];
    float* out = (float*)d_out;

    float *h1, *h2, *s2, *h3, *ft, *Bt, *part;
    cudaGetSymbolAddress((void**)&h1,   g_h1);
    cudaGetSymbolAddress((void**)&h2,   g_h2);
    cudaGetSymbolAddress((void**)&s2,   g_s2);
    cudaGetSymbolAddress((void**)&h3,   g_h3);
    cudaGetSymbolAddress((void**)&ft,   g_ft);
    cudaGetSymbolAddress((void**)&Bt,   g_Bt);
    cudaGetSymbolAddress((void**)&part, g_part);

    cudaFuncSetAttribute(k_dense, cudaFuncAttributeMaxDynamicSharedMemorySize,
                         DKS*BB*4);

    k_tw2   <<<KA3, C2>>>(w2, Bt);
    k_conv0 <<<P0/4, 256>>>(x, nb0, w0, bias0, ww0, h1);
    k_pool1 <<<P1, 128>>>(h1, nb1, pnb1, h2);
    k_s2    <<<P1, 256>>>(h2, nb2, ww2, s2);
    k_gemm  <<<NBLK, 256>>>(s2, Bt, bias2, h3);
    k_pool3 <<<P2, 128>>>(h3, nb3, pnb3, ft);
    k_dense <<<16*SPLITD, 256, DKS*BB*4>>>(Wm, Ws, ft, part);
    k_reduce<<<16, 256>>>(part, bm, bs, out);
}

// round 12
// speedup vs baseline: 1.8453x; 1.1367x over previous
#include <cuda_runtime.h>
#include <cuda_bf16.h>
#include <cstdint>

// Shapes
#define BB 8
#define P0 20000
#define P1 5000
#define P2 1250
#define MM 10
#define WW 9
#define C0 3
#define C1 64
#define C2 128
#define LATENT 256
#define FDIM (P2*C2)      // 160000
#define KA3 (WW*C1)       // 576
#define NROWS (BB*P1)     // 40000
#define GBM 128
#define NBLK 313          // ceil(40000/128)
#define AROWS (NBLK*GBM)  // 40064 (padded rows; tail garbage, stores guarded)

typedef unsigned long long ull;

// ---------------- scratch (device globals; no allocation) ----------------
__device__ float g_h1[BB*P0*C1];        // 10.24M
__device__ float g_h2[BB*P1*C1];        // 2.56M
__device__ float g_s2[(long)AROWS*KA3]; // 23.08M floats
__device__ float g_h3[BB*P1*C2];        // 5.12M
__device__ float g_ft[FDIM*BB];         // 1.28M  (f transposed: [k][b])
__device__ float g_BT[C2*KA3];          // 73728  (B^T: [n][k])
#define SPLITD 100
#define DKS    1600                      // FDIM / SPLITD
__device__ float g_part[SPLITD*512*BB];  // 409600

__device__ __forceinline__ float eluf(float x){
    return x > 0.f ? x : (expf(x) - 1.f);
}

// ---------------- packed f32x2 helpers ----------------
__device__ __forceinline__ ull pk2(float lo, float hi){
    ull r; asm("mov.b64 %0, {%1,%2};" : "=l"(r) : "f"(lo), "f"(hi)); return r;
}
__device__ __forceinline__ void fma2(ull &d, ull a, ull b){
    asm("fma.rn.f32x2 %0, %1, %2, %0;" : "+l"(d) : "l"(a), "l"(b));
}
__device__ __forceinline__ ull add2(ull a, ull b){
    ull r; asm("add.rn.f32x2 %0, %1, %2;" : "=l"(r) : "l"(a), "l"(b)); return r;
}
__device__ __forceinline__ float2 upk2(ull v){
    float2 f; asm("mov.b64 {%0,%1}, %2;" : "=f"(f.x), "=f"(f.y) : "l"(v)); return f;
}
// pack two bf16 (from floats) into b32: lo = a, hi = b
__device__ __forceinline__ uint32_t bfpack(float a, float b){
    __nv_bfloat162 h = __floats2bfloat162_rn(a, b);
    return *(uint32_t*)&h;
}

// ---------------- stage 1: full_conv0 + elu ----------------
__global__ void __launch_bounds__(256) k_conv0(
    const float* __restrict__ x, const int* __restrict__ nb0,
    const float* __restrict__ w0, const float* __restrict__ bias0,
    const float* __restrict__ ww0, float* __restrict__ h1)
{
    const int PTS = 4;
    __shared__ float sw0[WW*C1*C0];
    __shared__ float nbh[PTS][BB][MM][C0];
    __shared__ float w2s[PTS][MM][WW];
    __shared__ float ssh[PTS][BB][28];
    __shared__ int   nbs[PTS][MM];

    const int tid = threadIdx.x;
    const int p0 = blockIdx.x * PTS;

    for (int i = tid; i < WW*C1*C0; i += 256) sw0[i] = w0[i];

    if (tid < PTS*MM) {
        int pt = tid / MM, m = tid % MM;
        int nb = nb0[(p0+pt)*MM + m];
        bool valid = (nb != P0);
        nbs[pt][m] = valid ? nb : 0;
        const float* wp = ww0 + ((long)(p0+pt)*MM + m)*WW;
        #pragma unroll
        for (int w = 0; w < WW; w++) w2s[pt][m][w] = valid ? wp[w] : 0.f;
    }
    __syncthreads();

    for (int idx = tid; idx < PTS*BB*MM; idx += 256) {
        int pt = idx / (BB*MM); int rem = idx % (BB*MM);
        int b = rem / MM, m = rem % MM;
        const float* xr = x + ((long)b*P0 + nbs[pt][m]) * C0;
        nbh[pt][b][m][0] = xr[0];
        nbh[pt][b][m][1] = xr[1];
        nbh[pt][b][m][2] = xr[2];
    }
    __syncthreads();

    for (int idx = tid; idx < PTS*BB*27; idx += 256) {
        int pt = idx / (BB*27); int rem = idx % (BB*27);
        int b = rem / 27, k = rem % 27;
        int w = k / 3, i = k % 3;
        float acc = 0.f;
        #pragma unroll
        for (int m = 0; m < MM; m++) acc += w2s[pt][m][w] * nbh[pt][b][m][i];
        ssh[pt][b][k] = acc;
    }
    __syncthreads();

    const int o = tid & 63;
    float wr[27];
    #pragma unroll
    for (int k = 0; k < 27; k++) {
        int w = k / 3, i = k % 3;
        wr[k] = sw0[w*(C1*C0) + o*3 + i];
    }
    const float bv = bias0[o];
    const int pairbase = tid >> 6;
    #pragma unroll
    for (int j = 0; j < 8; j++) {
        int pair = pairbase + j*4;
        int pt = pair >> 3, b = pair & 7;
        float acc = bv;
        #pragma unroll
        for (int k = 0; k < 27; k++) acc += wr[k] * ssh[pt][b][k];
        h1[((long)b*P0 + p0 + pt)*C1 + o] = eluf(acc);
    }
}

// ---------------- stage 2: pool1 + elu ----------------
__global__ void __launch_bounds__(128) k_pool1(
    const float* __restrict__ h1, const int* __restrict__ nb1,
    const float* __restrict__ pnb, float* __restrict__ h2)
{
    __shared__ float pn[MM];
    __shared__ int nbs[MM];
    const int p = blockIdx.x, tid = threadIdx.x;
    if (tid < MM) {
        int nb = nb1[p*MM + tid];
        bool valid = (nb != P0);
        nbs[tid] = valid ? nb : 0;
        pn[tid]  = valid ? fabsf(pnb[p*MM + tid]) : 0.f;
    }
    __syncthreads();
    float den = 1e-8f;
    #pragma unroll
    for (int m = 0; m < MM; m++) den += pn[m];
    const float inv = 1.f / den;

    for (int idx = tid; idx < BB*C1; idx += 128) {
        int b = idx >> 6, c = idx & 63;
        float acc = 0.f;
        #pragma unroll
        for (int m = 0; m < MM; m++)
            acc += pn[m] * h1[((long)b*P0 + nbs[m])*C1 + c];
        h2[((long)b*P1 + p)*C1 + c] = eluf(acc * inv);
    }
}

// ---------------- stage 3a: s2[b*P1+p][w*64+i], f32x2 tap accumulation ----------------
__global__ void __launch_bounds__(256) k_s2(
    const float* __restrict__ h2, const int* __restrict__ nb2,
    const float* __restrict__ ww2, float* __restrict__ s2)
{
    __shared__ float nbh[BB][MM][C1];  // 20KB
    __shared__ float w2s[MM][WW];
    __shared__ int nbs[MM];
    const int p = blockIdx.x, tid = threadIdx.x;
    if (tid < MM) {
        int nb = nb2[p*MM + tid];
        nbs[tid] = (nb != P1) ? nb : -1;
    }
    __syncthreads();
    if (tid < MM*WW) {
        int m = tid / WW, w = tid % WW;
        w2s[m][w] = (nbs[m] >= 0) ? ww2[((long)p*MM + m)*WW + w] : 0.f;
    }
    for (int idx = tid; idx < BB*MM*C1; idx += 256) {
        int b = idx / (MM*C1); int rem = idx % (MM*C1);
        int m = rem / C1, i = rem & 63;
        int nb = nbs[m];
        nbh[b][m][i] = (nb >= 0) ? h2[((long)b*P1 + nb)*C1 + i] : 0.f;
    }
    __syncthreads();
    for (int idx = tid; idx < BB*(KA3/2); idx += 256) {
        int b  = idx / (KA3/2);
        int k2 = idx - b*(KA3/2);        // 0..287
        int w  = k2 >> 5;                // 0..8
        int i  = (k2 & 31) << 1;         // even 0..62
        const float* nbb = &nbh[b][0][i];
        ull acc = 0ULL;
        #pragma unroll
        for (int m = 0; m < MM; m++) {
            float wv = w2s[m][w];
            fma2(acc, pk2(wv, wv), *(const ull*)(nbb + m*C1));
        }
        *(ull*)&s2[(long)(b*P1 + p)*KA3 + (k2 << 1)] = acc;
    }
}

// ---------------- weights2 transpose: BT[o][w*64+i] ----------------
__global__ void k_tw2(const float* __restrict__ w2g, float* __restrict__ BT){
    int k = blockIdx.x;   // 576
    int o = threadIdx.x;  // 128
    int w = k >> 6, i = k & 63;
    BT[o*KA3 + k] = w2g[w*(C2*C1) + o*C1 + i];
}

// ---------------- stage 3b: HMMA split-bf16 GEMM + bias + elu ----------------
// C[r,o] = elu(bias[o] + sum_k A[r,k]*BT[o,k]),  A,B fp32 split to bf16 hi/lo
// smem per buffer (64KB): AH 16K | AL 16K | BH 16K | BL 16K, fragment-packed.
#define MMA_SMEM (2*65536)

#define MMA_BF16(c, a, b) \
    asm volatile("mma.sync.aligned.m16n8k16.row.col.f32.bf16.bf16.f32 " \
        "{%0,%1,%2,%3}, {%4,%5,%6,%7}, {%8,%9}, {%0,%1,%2,%3};" \
        : "+f"(c[0]), "+f"(c[1]), "+f"(c[2]), "+f"(c[3]) \
        : "r"(a.x), "r"(a.y), "r"(a.z), "r"(a.w), "r"(b.x), "r"(b.y))

__global__ void __launch_bounds__(256) k_mma(
    const float* __restrict__ A, const float* __restrict__ BT,
    const float* __restrict__ bias, float* __restrict__ C)
{
    extern __shared__ __align__(16) char sm[];
    const int tid = threadIdx.x;
    const int wid = tid >> 5, lane = tid & 31;
    const int mw = wid & 3, nw = wid >> 2;
    const long r0 = (long)blockIdx.x * GBM;

    float c[2][8][4];
    #pragma unroll
    for (int rb = 0; rb < 2; rb++)
        #pragma unroll
        for (int j = 0; j < 8; j++)
            #pragma unroll
            for (int q = 0; q < 4; q++) c[rb][j][q] = 0.f;

    const int g = lane >> 2, tc = lane & 3;

    // ---- staging lambda-ish (macro'd by chunk, buffer) ----
    // A: 4096 pairs; B: 4096 pairs. idx = row*32 + p.
    #define STAGE_CHUNK(kc, bufo) do {                                          \
        const float* Abase = A + r0*KA3 + (kc)*64;                              \
        const float* Bbase = BT + (kc)*64;                                      \
        _Pragma("unroll")                                                       \
        for (int it = 0; it < 16; it++) {                                       \
            int idx = tid + it*256;                                             \
            int row = idx >> 5, p = idx & 31;                                   \
            float2 v = *(const float2*)(Abase + (long)row*KA3 + 2*p);           \
            uint32_t hi = bfpack(v.x, v.y);                                     \
            __nv_bfloat162 hv = *(__nv_bfloat162*)&hi;                          \
            uint32_t lo = bfpack(v.x - __bfloat162float(hv.x),                  \
                                 v.y - __bfloat162float(hv.y));                 \
            int kstep = p >> 3, pl = p & 7, tcc = pl & 3, ksel = pl >> 2;       \
            int rblk = row >> 4, r16 = row & 15, gg = r16 & 7, half = r16 >> 3; \
            int reg = ksel*2 + half, ln = gg*4 + tcc;                           \
            uint32_t* dst = (uint32_t*)(sm + (bufo) + (kstep*8 + rblk)*512) + ln*4 + reg; \
            dst[0] = hi;                                                        \
            *(uint32_t*)((char*)dst + 16384) = lo;                              \
        }                                                                       \
        _Pragma("unroll")                                                       \
        for (int it = 0; it < 16; it++) {                                       \
            int idx = tid + it*256;                                             \
            int n = idx >> 5, p = idx & 31;                                     \
            float2 v = *(const float2*)(Bbase + (long)n*KA3 + 2*p);             \
            uint32_t hi = bfpack(v.x, v.y);                                     \
            __nv_bfloat162 hv = *(__nv_bfloat162*)&hi;                          \
            uint32_t lo = bfpack(v.x - __bfloat162float(hv.x),                  \
                                 v.y - __bfloat162float(hv.y));                 \
            int kstep = p >> 3, pl = p & 7, tcc = pl & 3, ksel = pl >> 2;       \
            int nblk = n >> 3, gg = n & 7;                                      \
            int ln = gg*4 + tcc;                                                \
            uint32_t* dst = (uint32_t*)(sm + (bufo) + 32768 + (kstep*16 + nblk)*256) + ln*2 + ksel; \
            dst[0] = hi;                                                        \
            *(uint32_t*)((char*)dst + 16384) = lo;                              \
        }                                                                       \
    } while(0)

    STAGE_CHUNK(0, 0);
    __syncthreads();

    const int rblk0 = mw*2, rblk1 = mw*2 + 1;
    const int nblk0 = nw*8;
    int bufo = 0;

    for (int kc = 0; kc < 9; kc++) {
        if (kc + 1 < 9) STAGE_CHUNK(kc + 1, bufo ^ 65536);
        const char* sb = sm + bufo;
        #pragma unroll
        for (int ks = 0; ks < 4; ks++) {
            uint4 ah0 = *(const uint4*)(sb + (ks*8 + rblk0)*512 + lane*16);
            uint4 ah1 = *(const uint4*)(sb + (ks*8 + rblk1)*512 + lane*16);
            uint4 al0 = *(const uint4*)(sb + 16384 + (ks*8 + rblk0)*512 + lane*16);
            uint4 al1 = *(const uint4*)(sb + 16384 + (ks*8 + rblk1)*512 + lane*16);
            uint2 bh[8], bl[8];
            #pragma unroll
            for (int j = 0; j < 8; j++) {
                bh[j] = *(const uint2*)(sb + 32768 + (ks*16 + nblk0 + j)*256 + lane*8);
                bl[j] = *(const uint2*)(sb + 49152 + (ks*16 + nblk0 + j)*256 + lane*8);
            }
            #pragma unroll
            for (int j = 0; j < 8; j++) { MMA_BF16(c[0][j], ah0, bh[j]); MMA_BF16(c[1][j], ah1, bh[j]); }
            #pragma unroll
            for (int j = 0; j < 8; j++) { MMA_BF16(c[0][j], ah0, bl[j]); MMA_BF16(c[1][j], ah1, bl[j]); }
            #pragma unroll
            for (int j = 0; j < 8; j++) { MMA_BF16(c[0][j], al0, bh[j]); MMA_BF16(c[1][j], al1, bh[j]); }
        }
        __syncthreads();
        bufo ^= 65536;
    }

    // epilogue: bias + elu
    #pragma unroll
    for (int rb = 0; rb < 2; rb++) {
        long row0 = r0 + (mw*2 + rb)*16 + g;      // c0,c1 row
        long row1 = row0 + 8;                      // c2,c3 row
        #pragma unroll
        for (int j = 0; j < 8; j++) {
            int col = nw*64 + j*8 + tc*2;
            float2 bia = *(const float2*)(bias + col);
            if (row0 < NROWS) {
                float2 o;
                o.x = eluf(c[rb][j][0] + bia.x);
                o.y = eluf(c[rb][j][1] + bia.y);
                *(float2*)&C[row0*C2 + col] = o;
            }
            if (row1 < NROWS) {
                float2 o;
                o.x = eluf(c[rb][j][2] + bia.x);
                o.y = eluf(c[rb][j][3] + bia.y);
                *(float2*)&C[row1*C2 + col] = o;
            }
        }
    }
    #undef STAGE_CHUNK
}

// ---------------- stage 4: pool3 + elu, writes f TRANSPOSED ft[k][b] ----------------
__global__ void __launch_bounds__(128) k_pool3(
    const float* __restrict__ h3, const int* __restrict__ nb3,
    const float* __restrict__ pnb, float* __restrict__ ft)
{
    __shared__ float pn[MM];
    __shared__ int nbs[MM];
    const int p = blockIdx.x, tid = threadIdx.x;
    if (tid < MM) {
        int nb = nb3[p*MM + tid];
        bool valid = (nb != P1);
        nbs[tid] = valid ? nb : 0;
        pn[tid]  = valid ? fabsf(pnb[p*MM + tid]) : 0.f;
    }
    __syncthreads();
    float den = 1e-8f;
    #pragma unroll
    for (int m = 0; m < MM; m++) den += pn[m];
    const float inv = 1.f / den;
    const int c = tid;
    float out[BB];
    #pragma unroll
    for (int b = 0; b < BB; b++) {
        float acc = 0.f;
        #pragma unroll
        for (int m = 0; m < MM; m++)
            acc += pn[m] * h3[((long)b*P1 + nbs[m])*C2 + c];
        out[b] = eluf(acc * inv);
    }
    float4* d = (float4*)(ft + ((long)p*C2 + c)*BB);
    d[0] = make_float4(out[0], out[1], out[2], out[3]);
    d[1] = make_float4(out[4], out[5], out[6], out[7]);
}

// ---------------- stage 5: dense head ----------------
__global__ void __launch_bounds__(256) k_dense(
    const float* __restrict__ Wm, const float* __restrict__ Ws,
    const float* __restrict__ ft, float* __restrict__ part)
{
    extern __shared__ float fs[];
    const int tid = threadIdx.x;
    const int rb = blockIdx.x & 15;
    const int sk = blockIdx.x >> 4;
    const int kbase = sk * DKS;

    {
        const float4* src = (const float4*)(ft + (long)kbase*BB);
        float4* dst = (float4*)fs;
        for (int i = tid; i < DKS*BB/4; i += 256) dst[i] = src[i];
    }
    __syncthreads();

    const int warp = tid >> 5, lane = tid & 31;
    const int l0 = rb*32 + warp*4;
    const float* Wb = (l0 < LATENT) ? (Wm + (long)l0*FDIM)
                                    : (Ws + (long)(l0 - LATENT)*FDIM);
    const float* W0 = Wb;
    const float* W1 = Wb + FDIM;
    const float* W2p = Wb + 2L*FDIM;
    const float* W3 = Wb + 3L*FDIM;

    const int kl = lane >> 1;
    const int h  = lane & 1;
    const float* fpb = fs + h*4;

    ull a00=0,a01=0,a10=0,a11=0,a20=0,a21=0,a30=0,a31=0;

    #pragma unroll 2
    for (int t = 0; t < DKS/16; t++) {
        int k = t*16 + kl;
        float4 fv = *(const float4*)(fpb + k*8);
        ull f01 = pk2(fv.x, fv.y);
        ull f23 = pk2(fv.z, fv.w);
        long kg = kbase + k;
        float w0 = W0[kg], w1 = W1[kg], w2v = W2p[kg], w3 = W3[kg];
        ull p0 = pk2(w0,w0), p1 = pk2(w1,w1), p2 = pk2(w2v,w2v), p3 = pk2(w3,w3);
        fma2(a00,p0,f01); fma2(a01,p0,f23);
        fma2(a10,p1,f01); fma2(a11,p1,f23);
        fma2(a20,p2,f01); fma2(a21,p2,f23);
        fma2(a30,p3,f01); fma2(a31,p3,f23);
    }

    #pragma unroll
    for (int ofs = 2; ofs < 32; ofs <<= 1) {
        a00 = add2(a00, __shfl_xor_sync(0xffffffffu, a00, ofs));
        a01 = add2(a01, __shfl_xor_sync(0xffffffffu, a01, ofs));
        a10 = add2(a10, __shfl_xor_sync(0xffffffffu, a10, ofs));
        a11 = add2(a11, __shfl_xor_sync(0xffffffffu, a11, ofs));
        a20 = add2(a20, __shfl_xor_sync(0xffffffffu, a20, ofs));
        a21 = add2(a21, __shfl_xor_sync(0xffffffffu, a21, ofs));
        a30 = add2(a30, __shfl_xor_sync(0xffffffffu, a30, ofs));
        a31 = add2(a31, __shfl_xor_sync(0xffffffffu, a31, ofs));
    }

    if (kl == 0) {
        float* dst = part + ((long)sk*512 + l0)*BB + h*4;
        float2 v;
        v=upk2(a00); dst[0]=v.x; dst[1]=v.y; v=upk2(a01); dst[2]=v.x; dst[3]=v.y;
        dst += BB;
        v=upk2(a10); dst[0]=v.x; dst[1]=v.y; v=upk2(a11); dst[2]=v.x; dst[3]=v.y;
        dst += BB;
        v=upk2(a20); dst[0]=v.x; dst[1]=v.y; v=upk2(a21); dst[2]=v.x; dst[3]=v.y;
        dst += BB;
        v=upk2(a30); dst[0]=v.x; dst[1]=v.y; v=upk2(a31); dst[2]=v.x; dst[3]=v.y;
    }
}

__global__ void __launch_bounds__(256) k_reduce(
    const float* __restrict__ part, const float* __restrict__ bm,
    const float* __restrict__ bs, float* __restrict__ out)
{
    int idx = blockIdx.x*256 + threadIdx.x;
    int l = idx >> 3, b = idx & 7;
    float acc = (l < LATENT) ? bm[l] : bs[l - LATENT];
    for (int sk = 0; sk < SPLITD; sk++) acc += part[((long)sk*512 + l)*BB + b];
    out[b*512 + l] = acc;
}

// ---------------- launch ----------------
extern "C" void kernel_launch(void* const* d_in, const int* in_sizes, int n_in,
                              void* d_out, int out_size)
{
    const float* x      = (const float*)d_in[0];
    const int*   nb0    = (const int*)  d_in[1];
    const int*   nb1    = (const int*)  d_in[2];
    const int*   nb2    = (const int*)  d_in[3];
    const int*   nb3    = (const int*)  d_in[4];
    const float* w0     = (const float*)d_in[5];
    const float* bias0  = (const float*)d_in[6];
    const float* ww0    = (const float*)d_in[7];
    const float* pnb1   = (const float*)d_in[8];
    const float* w2     = (const float*)d_in[9];
    const float* bias2  = (const float*)d_in[10];
    const float* ww2    = (const float*)d_in[11];
    const float* pnb3   = (const float*)d_in[12];
    const float* Wm     = (const float*)d_in[13];
    const float* bm     = (const float*)d_in[14];
    const float* Ws     = (const float*)d_in[15];
    const float* bs     = (const float*)d_in[16];
    float* out = (float*)d_out;

    float *h1, *h2, *s2, *h3, *ft, *BT, *part;
    cudaGetSymbolAddress((void**)&h1,   g_h1);
    cudaGetSymbolAddress((void**)&h2,   g_h2);
    cudaGetSymbolAddress((void**)&s2,   g_s2);
    cudaGetSymbolAddress((void**)&h3,   g_h3);
    cudaGetSymbolAddress((void**)&ft,   g_ft);
    cudaGetSymbolAddress((void**)&BT,   g_BT);
    cudaGetSymbolAddress((void**)&part, g_part);

    cudaFuncSetAttribute(k_mma, cudaFuncAttributeMaxDynamicSharedMemorySize, MMA_SMEM);
    cudaFuncSetAttribute(k_dense, cudaFuncAttributeMaxDynamicSharedMemorySize, DKS*BB*4);

    k_tw2   <<<KA3, C2>>>(w2, BT);
    k_conv0 <<<P0/4, 256>>>(x, nb0, w0, bias0, ww0, h1);
    k_pool1 <<<P1, 128>>>(h1, nb1, pnb1, h2);
    k_s2    <<<P1, 256>>>(h2, nb2, ww2, s2);
    k_mma   <<<NBLK, 256, MMA_SMEM>>>(s2, BT, bias2, h3);
    k_pool3 <<<P2, 128>>>(h3, nb3, pnb3, ft);
    k_dense <<<16*SPLITD, 256, DKS*BB*4>>>(Wm, Ws, ft, part);
    k_reduce<<<16, 256>>>(part, bm, bs, out);
}

// round 13
// speedup vs baseline: 1.8732x; 1.0151x over previous
#include <cuda_runtime.h>
#include <cuda_bf16.h>
#include <cstdint>

// Shapes
#define BB 8
#define P0 20000
#define P1 5000
#define P2 1250
#define MM 10
#define WW 9
#define C0 3
#define C1 64
#define C2 128
#define LATENT 256
#define FDIM (P2*C2)      // 160000
#define KA3 (WW*C1)       // 576
#define NROWS (BB*P1)     // 40000
#define GBM 128
#define NBLK 313          // ceil(40000/128)
#define AROWS (NBLK*GBM)  // 40064 (padded rows; tail garbage, stores guarded)

typedef unsigned long long ull;

// ---------------- scratch (device globals; no allocation) ----------------
__device__ float g_h1[BB*P0*C1];        // 10.24M
__device__ float g_h2[BB*P1*C1];        // 2.56M
__device__ float g_s2[(long)AROWS*KA3]; // 23.08M floats
__device__ float g_h3[BB*P1*C2];        // 5.12M
__device__ float g_ft[FDIM*BB];         // 1.28M  (f transposed: [k][b])
__device__ float g_BT[C2*KA3];          // 73728  (B^T: [n][k])
#define SPLITD 100
#define DKS    1600                      // FDIM / SPLITD
__device__ float g_part[SPLITD*512*BB];  // 409600

__device__ __forceinline__ float eluf(float x){
    return x > 0.f ? x : (expf(x) - 1.f);
}

// ---------------- packed f32x2 helpers ----------------
__device__ __forceinline__ ull pk2(float lo, float hi){
    ull r; asm("mov.b64 %0, {%1,%2};" : "=l"(r) : "f"(lo), "f"(hi)); return r;
}
__device__ __forceinline__ void fma2(ull &d, ull a, ull b){
    asm("fma.rn.f32x2 %0, %1, %2, %0;" : "+l"(d) : "l"(a), "l"(b));
}
__device__ __forceinline__ ull add2(ull a, ull b){
    ull r; asm("add.rn.f32x2 %0, %1, %2;" : "=l"(r) : "l"(a), "l"(b)); return r;
}
__device__ __forceinline__ float2 upk2(ull v){
    float2 f; asm("mov.b64 {%0,%1}, %2;" : "=f"(f.x), "=f"(f.y) : "l"(v)); return f;
}
// pack two bf16 (from floats) into b32: lo = a, hi = b
__device__ __forceinline__ uint32_t bfpack(float a, float b){
    __nv_bfloat162 h = __floats2bfloat162_rn(a, b);
    return *(uint32_t*)&h;
}

// ---------------- stage 1: full_conv0 + elu ----------------
__global__ void __launch_bounds__(256) k_conv0(
    const float* __restrict__ x, const int* __restrict__ nb0,
    const float* __restrict__ w0, const float* __restrict__ bias0,
    const float* __restrict__ ww0, float* __restrict__ h1)
{
    const int PTS = 4;
    __shared__ float sw0[WW*C1*C0];
    __shared__ float nbh[PTS][BB][MM][C0];
    __shared__ float w2s[PTS][MM][WW];
    __shared__ float ssh[PTS][BB][28];
    __shared__ int   nbs[PTS][MM];

    const int tid = threadIdx.x;
    const int p0 = blockIdx.x * PTS;

    for (int i = tid; i < WW*C1*C0; i += 256) sw0[i] = w0[i];

    if (tid < PTS*MM) {
        int pt = tid / MM, m = tid % MM;
        int nb = nb0[(p0+pt)*MM + m];
        bool valid = (nb != P0);
        nbs[pt][m] = valid ? nb : 0;
        const float* wp = ww0 + ((long)(p0+pt)*MM + m)*WW;
        #pragma unroll
        for (int w = 0; w < WW; w++) w2s[pt][m][w] = valid ? wp[w] : 0.f;
    }
    __syncthreads();

    for (int idx = tid; idx < PTS*BB*MM; idx += 256) {
        int pt = idx / (BB*MM); int rem = idx % (BB*MM);
        int b = rem / MM, m = rem % MM;
        const float* xr = x + ((long)b*P0 + nbs[pt][m]) * C0;
        nbh[pt][b][m][0] = xr[0];
        nbh[pt][b][m][1] = xr[1];
        nbh[pt][b][m][2] = xr[2];
    }
    __syncthreads();

    for (int idx = tid; idx < PTS*BB*27; idx += 256) {
        int pt = idx / (BB*27); int rem = idx % (BB*27);
        int b = rem / 27, k = rem % 27;
        int w = k / 3, i = k % 3;
        float acc = 0.f;
        #pragma unroll
        for (int m = 0; m < MM; m++) acc += w2s[pt][m][w] * nbh[pt][b][m][i];
        ssh[pt][b][k] = acc;
    }
    __syncthreads();

    const int o = tid & 63;
    float wr[27];
    #pragma unroll
    for (int k = 0; k < 27; k++) {
        int w = k / 3, i = k % 3;
        wr[k] = sw0[w*(C1*C0) + o*3 + i];
    }
    const float bv = bias0[o];
    const int pairbase = tid >> 6;
    #pragma unroll
    for (int j = 0; j < 8; j++) {
        int pair = pairbase + j*4;
        int pt = pair >> 3, b = pair & 7;
        float acc = bv;
        #pragma unroll
        for (int k = 0; k < 27; k++) acc += wr[k] * ssh[pt][b][k];
        h1[((long)b*P0 + p0 + pt)*C1 + o] = eluf(acc);
    }
}

// ---------------- stage 2: pool1 + elu ----------------
__global__ void __launch_bounds__(128) k_pool1(
    const float* __restrict__ h1, const int* __restrict__ nb1,
    const float* __restrict__ pnb, float* __restrict__ h2)
{
    __shared__ float pn[MM];
    __shared__ int nbs[MM];
    const int p = blockIdx.x, tid = threadIdx.x;
    if (tid < MM) {
        int nb = nb1[p*MM + tid];
        bool valid = (nb != P0);
        nbs[tid] = valid ? nb : 0;
        pn[tid]  = valid ? fabsf(pnb[p*MM + tid]) : 0.f;
    }
    __syncthreads();
    float den = 1e-8f;
    #pragma unroll
    for (int m = 0; m < MM; m++) den += pn[m];
    const float inv = 1.f / den;

    for (int idx = tid; idx < BB*C1; idx += 128) {
        int b = idx >> 6, c = idx & 63;
        float acc = 0.f;
        #pragma unroll
        for (int m = 0; m < MM; m++)
            acc += pn[m] * h1[((long)b*P0 + nbs[m])*C1 + c];
        h2[((long)b*P1 + p)*C1 + c] = eluf(acc * inv);
    }
}

// ---------------- stage 3a: s2, one thread per (b, channel-pair) ----------------
// thread loads its 10 neighbor f32x2 once, emits all 9 w outputs.
__global__ void __launch_bounds__(256) k_s2(
    const float* __restrict__ h2, const int* __restrict__ nb2,
    const float* __restrict__ ww2, float* __restrict__ s2)
{
    __shared__ float nbh[BB][MM][C1];  // 20KB
    __shared__ float w2s[MM][WW];
    __shared__ int nbs[MM];
    const int p = blockIdx.x, tid = threadIdx.x;
    if (tid < MM) {
        int nb = nb2[p*MM + tid];
        nbs[tid] = (nb != P1) ? nb : -1;
    }
    __syncthreads();
    if (tid < MM*WW) {
        int m = tid / WW, w = tid % WW;
        w2s[m][w] = (nbs[m] >= 0) ? ww2[((long)p*MM + m)*WW + w] : 0.f;
    }
    // gather: 80 rows x 64 floats, float4 loads (1280 float4)
    for (int idx = tid; idx < BB*MM*(C1/4); idx += 256) {
        int b = idx / (MM*(C1/4)); int rem = idx % (MM*(C1/4));
        int m = rem / (C1/4), i4 = rem & 15;
        int nb = nbs[m];
        float4 v = make_float4(0.f,0.f,0.f,0.f);
        if (nb >= 0) v = *(const float4*)(h2 + ((long)b*P1 + nb)*C1 + i4*4);
        *(float4*)&nbh[b][m][i4*4] = v;
    }
    __syncthreads();

    // 256 threads == BB * 32 channel-pairs
    const int b  = tid >> 5;          // 0..7
    const int ip = tid & 31;          // pair index, i = 2*ip
    const float* nbb = &nbh[b][0][2*ip];
    ull v[MM];
    #pragma unroll
    for (int m = 0; m < MM; m++) v[m] = *(const ull*)(nbb + m*C1);

    float* orow = s2 + (long)(b*P1 + p)*KA3 + 2*ip;
    #pragma unroll
    for (int w = 0; w < WW; w++) {
        ull acc = 0ULL;
        #pragma unroll
        for (int m = 0; m < MM; m++) {
            float wv = w2s[m][w];
            fma2(acc, pk2(wv, wv), v[m]);
        }
        *(ull*)(orow + w*C1) = acc;
    }
}

// ---------------- weights2 transpose: BT[o][w*64+i] ----------------
__global__ void k_tw2(const float* __restrict__ w2g, float* __restrict__ BT){
    int k = blockIdx.x;   // 576
    int o = threadIdx.x;  // 128
    int w = k >> 6, i = k & 63;
    BT[o*KA3 + k] = w2g[w*(C2*C1) + o*C1 + i];
}

// ---------------- stage 3b: HMMA split-bf16 GEMM + bias + elu ----------------
// C[r,o] = elu(bias[o] + sum_k A[r,k]*BT[o,k]),  A,B fp32 split to bf16 hi/lo
// smem per buffer (64KB): AH 16K | AL 16K | BH 16K | BL 16K, fragment-packed.
#define MMA_SMEM (2*65536)

#define MMA_BF16(c, a, b) \
    asm volatile("mma.sync.aligned.m16n8k16.row.col.f32.bf16.bf16.f32 " \
        "{%0,%1,%2,%3}, {%4,%5,%6,%7}, {%8,%9}, {%0,%1,%2,%3};" \
        : "+f"(c[0]), "+f"(c[1]), "+f"(c[2]), "+f"(c[3]) \
        : "r"(a.x), "r"(a.y), "r"(a.z), "r"(a.w), "r"(b.x), "r"(b.y))

__global__ void __launch_bounds__(256) k_mma(
    const float* __restrict__ A, const float* __restrict__ BT,
    const float* __restrict__ bias, float* __restrict__ C)
{
    extern __shared__ __align__(16) char sm[];
    const int tid = threadIdx.x;
    const int wid = tid >> 5, lane = tid & 31;
    const int mw = wid & 3, nw = wid >> 2;
    const long r0 = (long)blockIdx.x * GBM;

    float c[2][8][4];
    #pragma unroll
    for (int rb = 0; rb < 2; rb++)
        #pragma unroll
        for (int j = 0; j < 8; j++)
            #pragma unroll
            for (int q = 0; q < 4; q++) c[rb][j][q] = 0.f;

    const int g = lane >> 2, tc = lane & 3;

    #define STAGE_CHUNK(kc, bufo) do {                                          \
        const float* Abase = A + r0*KA3 + (kc)*64;                              \
        const float* Bbase = BT + (kc)*64;                                      \
        _Pragma("unroll")                                                       \
        for (int it = 0; it < 16; it++) {                                       \
            int idx = tid + it*256;                                             \
            int row = idx >> 5, p = idx & 31;                                   \
            float2 v = *(const float2*)(Abase + (long)row*KA3 + 2*p);           \
            uint32_t hi = bfpack(v.x, v.y);                                     \
            __nv_bfloat162 hv = *(__nv_bfloat162*)&hi;                          \
            uint32_t lo = bfpack(v.x - __bfloat162float(hv.x),                  \
                                 v.y - __bfloat162float(hv.y));                 \
            int kstep = p >> 3, pl = p & 7, tcc = pl & 3, ksel = pl >> 2;       \
            int rblk = row >> 4, r16 = row & 15, gg = r16 & 7, half = r16 >> 3; \
            int reg = ksel*2 + half, ln = gg*4 + tcc;                           \
            uint32_t* dst = (uint32_t*)(sm + (bufo) + (kstep*8 + rblk)*512) + ln*4 + reg; \
            dst[0] = hi;                                                        \
            *(uint32_t*)((char*)dst + 16384) = lo;                              \
        }                                                                       \
        _Pragma("unroll")                                                       \
        for (int it = 0; it < 16; it++) {                                       \
            int idx = tid + it*256;                                             \
            int n = idx >> 5, p = idx & 31;                                     \
            float2 v = *(const float2*)(Bbase + (long)n*KA3 + 2*p);             \
            uint32_t hi = bfpack(v.x, v.y);                                     \
            __nv_bfloat162 hv = *(__nv_bfloat162*)&hi;                          \
            uint32_t lo = bfpack(v.x - __bfloat162float(hv.x),                  \
                                 v.y - __bfloat162float(hv.y));                 \
            int kstep = p >> 3, pl = p & 7, tcc = pl & 3, ksel = pl >> 2;       \
            int nblk = n >> 3, gg = n & 7;                                      \
            int ln = gg*4 + tcc;                                                \
            uint32_t* dst = (uint32_t*)(sm + (bufo) + 32768 + (kstep*16 + nblk)*256) + ln*2 + ksel; \
            dst[0] = hi;                                                        \
            *(uint32_t*)((char*)dst + 16384) = lo;                              \
        }                                                                       \
    } while(0)

    STAGE_CHUNK(0, 0);
    __syncthreads();

    const int rblk0 = mw*2, rblk1 = mw*2 + 1;
    const int nblk0 = nw*8;
    int bufo = 0;

    for (int kc = 0; kc < 9; kc++) {
        if (kc + 1 < 9) STAGE_CHUNK(kc + 1, bufo ^ 65536);
        const char* sb = sm + bufo;
        #pragma unroll
        for (int ks = 0; ks < 4; ks++) {
            uint4 ah0 = *(const uint4*)(sb + (ks*8 + rblk0)*512 + lane*16);
            uint4 ah1 = *(const uint4*)(sb + (ks*8 + rblk1)*512 + lane*16);
            uint4 al0 = *(const uint4*)(sb + 16384 + (ks*8 + rblk0)*512 + lane*16);
            uint4 al1 = *(const uint4*)(sb + 16384 + (ks*8 + rblk1)*512 + lane*16);
            uint2 bh[8], bl[8];
            #pragma unroll
            for (int j = 0; j < 8; j++) {
                bh[j] = *(const uint2*)(sb + 32768 + (ks*16 + nblk0 + j)*256 + lane*8);
                bl[j] = *(const uint2*)(sb + 49152 + (ks*16 + nblk0 + j)*256 + lane*8);
            }
            #pragma unroll
            for (int j = 0; j < 8; j++) { MMA_BF16(c[0][j], ah0, bh[j]); MMA_BF16(c[1][j], ah1, bh[j]); }
            #pragma unroll
            for (int j = 0; j < 8; j++) { MMA_BF16(c[0][j], ah0, bl[j]); MMA_BF16(c[1][j], ah1, bl[j]); }
            #pragma unroll
            for (int j = 0; j < 8; j++) { MMA_BF16(c[0][j], al0, bh[j]); MMA_BF16(c[1][j], al1, bh[j]); }
        }
        __syncthreads();
        bufo ^= 65536;
    }

    // epilogue: bias + elu
    #pragma unroll
    for (int rb = 0; rb < 2; rb++) {
        long row0 = r0 + (mw*2 + rb)*16 + g;
        long row1 = row0 + 8;
        #pragma unroll
        for (int j = 0; j < 8; j++) {
            int col = nw*64 + j*8 + tc*2;
            float2 bia = *(const float2*)(bias + col);
            if (row0 < NROWS) {
                float2 o;
                o.x = eluf(c[rb][j][0] + bia.x);
                o.y = eluf(c[rb][j][1] + bia.y);
                *(float2*)&C[row0*C2 + col] = o;
            }
            if (row1 < NROWS) {
                float2 o;
                o.x = eluf(c[rb][j][2] + bia.x);
                o.y = eluf(c[rb][j][3] + bia.y);
                *(float2*)&C[row1*C2 + col] = o;
            }
        }
    }
    #undef STAGE_CHUNK
}

// ---------------- stage 4: pool3 + elu, writes f TRANSPOSED ft[k][b] ----------------
__global__ void __launch_bounds__(128) k_pool3(
    const float* __restrict__ h3, const int* __restrict__ nb3,
    const float* __restrict__ pnb, float* __restrict__ ft)
{
    __shared__ float pn[MM];
    __shared__ int nbs[MM];
    const int p = blockIdx.x, tid = threadIdx.x;
    if (tid < MM) {
        int nb = nb3[p*MM + tid];
        bool valid = (nb != P1);
        nbs[tid] = valid ? nb : 0;
        pn[tid]  = valid ? fabsf(pnb[p*MM + tid]) : 0.f;
    }
    __syncthreads();
    float den = 1e-8f;
    #pragma unroll
    for (int m = 0; m < MM; m++) den += pn[m];
    const float inv = 1.f / den;
    const int c = tid;
    float out[BB];
    #pragma unroll
    for (int b = 0; b < BB; b++) {
        float acc = 0.f;
        #pragma unroll
        for (int m = 0; m < MM; m++)
            acc += pn[m] * h3[((long)b*P1 + nbs[m])*C2 + c];
        out[b] = eluf(acc * inv);
    }
    float4* d = (float4*)(ft + ((long)p*C2 + c)*BB);
    d[0] = make_float4(out[0], out[1], out[2], out[3]);
    d[1] = make_float4(out[4], out[5], out[6], out[7]);
}

// ---------------- stage 5: dense head ----------------
__global__ void __launch_bounds__(256) k_dense(
    const float* __restrict__ Wm, const float* __restrict__ Ws,
    const float* __restrict__ ft, float* __restrict__ part)
{
    extern __shared__ float fs[];
    const int tid = threadIdx.x;
    const int rb = blockIdx.x & 15;
    const int sk = blockIdx.x >> 4;
    const int kbase = sk * DKS;

    {
        const float4* src = (const float4*)(ft + (long)kbase*BB);
        float4* dst = (float4*)fs;
        for (int i = tid; i < DKS*BB/4; i += 256) dst[i] = src[i];
    }
    __syncthreads();

    const int warp = tid >> 5, lane = tid & 31;
    const int l0 = rb*32 + warp*4;
    const float* Wb = (l0 < LATENT) ? (Wm + (long)l0*FDIM)
                                    : (Ws + (long)(l0 - LATENT)*FDIM);
    const float* W0 = Wb;
    const float* W1 = Wb + FDIM;
    const float* W2p = Wb + 2L*FDIM;
    const float* W3 = Wb + 3L*FDIM;

    const int kl = lane >> 1;
    const int h  = lane & 1;
    const float* fpb = fs + h*4;

    ull a00=0,a01=0,a10=0,a11=0,a20=0,a21=0,a30=0,a31=0;

    #pragma unroll 2
    for (int t = 0; t < DKS/16; t++) {
        int k = t*16 + kl;
        float4 fv = *(const float4*)(fpb + k*8);
        ull f01 = pk2(fv.x, fv.y);
        ull f23 = pk2(fv.z, fv.w);
        long kg = kbase + k;
        float w0 = W0[kg], w1 = W1[kg], w2v = W2p[kg], w3 = W3[kg];
        ull p0 = pk2(w0,w0), p1 = pk2(w1,w1), p2 = pk2(w2v,w2v), p3 = pk2(w3,w3);
        fma2(a00,p0,f01); fma2(a01,p0,f23);
        fma2(a10,p1,f01); fma2(a11,p1,f23);
        fma2(a20,p2,f01); fma2(a21,p2,f23);
        fma2(a30,p3,f01); fma2(a31,p3,f23);
    }

    #pragma unroll
    for (int ofs = 2; ofs < 32; ofs <<= 1) {
        a00 = add2(a00, __shfl_xor_sync(0xffffffffu, a00, ofs));
        a01 = add2(a01, __shfl_xor_sync(0xffffffffu, a01, ofs));
        a10 = add2(a10, __shfl_xor_sync(0xffffffffu, a10, ofs));
        a11 = add2(a11, __shfl_xor_sync(0xffffffffu, a11, ofs));
        a20 = add2(a20, __shfl_xor_sync(0xffffffffu, a20, ofs));
        a21 = add2(a21, __shfl_xor_sync(0xffffffffu, a21, ofs));
        a30 = add2(a30, __shfl_xor_sync(0xffffffffu, a30, ofs));
        a31 = add2(a31, __shfl_xor_sync(0xffffffffu, a31, ofs));
    }

    if (kl == 0) {
        float* dst = part + ((long)sk*512 + l0)*BB + h*4;
        float2 v;
        v=upk2(a00); dst[0]=v.x; dst[1]=v.y; v=upk2(a01); dst[2]=v.x; dst[3]=v.y;
        dst += BB;
        v=upk2(a10); dst[0]=v.x; dst[1]=v.y; v=upk2(a11); dst[2]=v.x; dst[3]=v.y;
        dst += BB;
        v=upk2(a20); dst[0]=v.x; dst[1]=v.y; v=upk2(a21); dst[2]=v.x; dst[3]=v.y;
        dst += BB;
        v=upk2(a30); dst[0]=v.x; dst[1]=v.y; v=upk2(a31); dst[2]=v.x; dst[3]=v.y;
    }
}

__global__ void __launch_bounds__(256) k_reduce(
    const float* __restrict__ part, const float* __restrict__ bm,
    const float* __restrict__ bs, float* __restrict__ out)
{
    int idx = blockIdx.x*256 + threadIdx.x;
    int l = idx >> 3, b = idx & 7;
    float acc = (l < LATENT) ? bm[l] : bs[l - LATENT];
    for (int sk = 0; sk < SPLITD; sk++) acc += part[((long)sk*512 + l)*BB + b];
    out[b*512 + l] = acc;
}

// ---------------- launch ----------------
extern "C" void kernel_launch(void* const* d_in, const int* in_sizes, int n_in,
                              void* d_out, int out_size)
{
    const float* x      = (const float*)d_in[0];
    const int*   nb0    = (const int*)  d_in[1];
    const int*   nb1    = (const int*)  d_in[2];
    const int*   nb2    = (const int*)  d_in[3];
    const int*   nb3    = (const int*)  d_in[4];
    const float* w0     = (const float*)d_in[5];
    const float* bias0  = (const float*)d_in[6];
    const float* ww0    = (const float*)d_in[7];
    const float* pnb1   = (const float*)d_in[8];
    const float* w2     = (const float*)d_in[9];
    const float* bias2  = (const float*)d_in[10];
    const float* ww2    = (const float*)d_in[11];
    const float* pnb3   = (const float*)d_in[12];
    const float* Wm     = (const float*)d_in[13];
    const float* bm     = (const float*)d_in[14];
    const float* Ws     = (const float*)d_in[15];
    const float* bs     = (const float*)d_in[16];
    float* out = (float*)d_out;

    float *h1, *h2, *s2, *h3, *ft, *BT, *part;
    cudaGetSymbolAddress((void**)&h1,   g_h1);
    cudaGetSymbolAddress((void**)&h2,   g_h2);
    cudaGetSymbolAddress((void**)&s2,   g_s2);
    cudaGetSymbolAddress((void**)&h3,   g_h3);
    cudaGetSymbolAddress((void**)&ft,   g_ft);
    cudaGetSymbolAddress((void**)&BT,   g_BT);
    cudaGetSymbolAddress((void**)&part, g_part);

    cudaFuncSetAttribute(k_mma, cudaFuncAttributeMaxDynamicSharedMemorySize, MMA_SMEM);
    cudaFuncSetAttribute(k_dense, cudaFuncAttributeMaxDynamicSharedMemorySize, DKS*BB*4);

    k_tw2   <<<KA3, C2>>>(w2, BT);
    k_conv0 <<<P0/4, 256>>>(x, nb0, w0, bias0, ww0, h1);
    k_pool1 <<<P1, 128>>>(h1, nb1, pnb1, h2);
    k_s2    <<<P1, 256>>>(h2, nb2, ww2, s2);
    k_mma   <<<NBLK, 256, MMA_SMEM>>>(s2, BT, bias2, h3);
    k_pool3 <<<P2, 128>>>(h3, nb3, pnb3, ft);
    k_dense <<<16*SPLITD, 256, DKS*BB*4>>>(Wm, Ws, ft, part);
    k_reduce<<<16, 256>>>(part, bm, bs, out);
}

// round 14
// speedup vs baseline: 1.9550x; 1.0437x over previous
#include <cuda_runtime.h>
#include <cuda_bf16.h>
#include <cstdint>

// Shapes
#define BB 8
#define P0 20000
#define P1 5000
#define P2 1250
#define MM 10
#define WW 9
#define C0 3
#define C1 64
#define C2 128
#define LATENT 256
#define FDIM (P2*C2)      // 160000
#define KA3 (WW*C1)       // 576
#define NROWS (BB*P1)     // 40000
#define GBM 128
#define NBLK 313          // ceil(40000/128)
#define AROWS (NBLK*GBM)  // 40064 (padded rows stay zero; stores guarded)

typedef unsigned long long ull;

// ---------------- scratch (device globals; no allocation) ----------------
__device__ float g_h1[BB*P0*C1];        // 10.24M
__device__ float g_h2[BB*P1*C1];        // 2.56M
__device__ __nv_bfloat16 g_Ah[(long)AROWS*KA3];   // 46MB
__device__ __nv_bfloat16 g_Al[(long)AROWS*KA3];   // 46MB
__device__ __nv_bfloat16 g_BTh[C2*KA3];
__device__ __nv_bfloat16 g_BTl[C2*KA3];
__device__ float g_h3[BB*P1*C2];        // 5.12M
__device__ float g_ft[FDIM*BB];         // 1.28M  (f transposed: [k][b])
#define SPLITD 100
#define DKS    1600                      // FDIM / SPLITD
__device__ float g_part[SPLITD*512*BB];  // 409600

__device__ __forceinline__ float eluf(float x){
    return x > 0.f ? x : (expf(x) - 1.f);
}

// ---------------- packed f32x2 helpers ----------------
__device__ __forceinline__ ull pk2(float lo, float hi){
    ull r; asm("mov.b64 %0, {%1,%2};" : "=l"(r) : "f"(lo), "f"(hi)); return r;
}
__device__ __forceinline__ void fma2(ull &d, ull a, ull b){
    asm("fma.rn.f32x2 %0, %1, %2, %0;" : "+l"(d) : "l"(a), "l"(b));
}
__device__ __forceinline__ ull add2(ull a, ull b){
    ull r; asm("add.rn.f32x2 %0, %1, %2;" : "=l"(r) : "l"(a), "l"(b)); return r;
}
__device__ __forceinline__ float2 upk2(ull v){
    float2 f; asm("mov.b64 {%0,%1}, %2;" : "=f"(f.x), "=f"(f.y) : "l"(v)); return f;
}
// pack two bf16 (from floats) into b32: lo = a, hi = b
__device__ __forceinline__ uint32_t bfpack(float a, float b){
    __nv_bfloat162 h = __floats2bfloat162_rn(a, b);
    return *(uint32_t*)&h;
}

// ---------------- stage 1: full_conv0 + elu ----------------
__global__ void __launch_bounds__(256) k_conv0(
    const float* __restrict__ x, const int* __restrict__ nb0,
    const float* __restrict__ w0, const float* __restrict__ bias0,
    const float* __restrict__ ww0, float* __restrict__ h1)
{
    const int PTS = 4;
    __shared__ float sw0[WW*C1*C0];
    __shared__ float nbh[PTS][BB][MM][C0];
    __shared__ float w2s[PTS][MM][WW];
    __shared__ float ssh[PTS][BB][28];
    __shared__ int   nbs[PTS][MM];

    const int tid = threadIdx.x;
    const int p0 = blockIdx.x * PTS;

    for (int i = tid; i < WW*C1*C0; i += 256) sw0[i] = w0[i];

    if (tid < PTS*MM) {
        int pt = tid / MM, m = tid % MM;
        int nb = nb0[(p0+pt)*MM + m];
        bool valid = (nb != P0);
        nbs[pt][m] = valid ? nb : 0;
        const float* wp = ww0 + ((long)(p0+pt)*MM + m)*WW;
        #pragma unroll
        for (int w = 0; w < WW; w++) w2s[pt][m][w] = valid ? wp[w] : 0.f;
    }
    __syncthreads();

    for (int idx = tid; idx < PTS*BB*MM; idx += 256) {
        int pt = idx / (BB*MM); int rem = idx % (BB*MM);
        int b = rem / MM, m = rem % MM;
        const float* xr = x + ((long)b*P0 + nbs[pt][m]) * C0;
        nbh[pt][b][m][0] = xr[0];
        nbh[pt][b][m][1] = xr[1];
        nbh[pt][b][m][2] = xr[2];
    }
    __syncthreads();

    for (int idx = tid; idx < PTS*BB*27; idx += 256) {
        int pt = idx / (BB*27); int rem = idx % (BB*27);
        int b = rem / 27, k = rem % 27;
        int w = k / 3, i = k % 3;
        float acc = 0.f;
        #pragma unroll
        for (int m = 0; m < MM; m++) acc += w2s[pt][m][w] * nbh[pt][b][m][i];
        ssh[pt][b][k] = acc;
    }
    __syncthreads();

    const int o = tid & 63;
    float wr[27];
    #pragma unroll
    for (int k = 0; k < 27; k++) {
        int w = k / 3, i = k % 3;
        wr[k] = sw0[w*(C1*C0) + o*3 + i];
    }
    const float bv = bias0[o];
    const int pairbase = tid >> 6;
    #pragma unroll
    for (int j = 0; j < 8; j++) {
        int pair = pairbase + j*4;
        int pt = pair >> 3, b = pair & 7;
        float acc = bv;
        #pragma unroll
        for (int k = 0; k < 27; k++) acc += wr[k] * ssh[pt][b][k];
        h1[((long)b*P0 + p0 + pt)*C1 + o] = eluf(acc);
    }
}

// ---------------- stage 2: pool1 + elu ----------------
__global__ void __launch_bounds__(128) k_pool1(
    const float* __restrict__ h1, const int* __restrict__ nb1,
    const float* __restrict__ pnb, float* __restrict__ h2)
{
    __shared__ float pn[MM];
    __shared__ int nbs[MM];
    const int p = blockIdx.x, tid = threadIdx.x;
    if (tid < MM) {
        int nb = nb1[p*MM + tid];
        bool valid = (nb != P0);
        nbs[tid] = valid ? nb : 0;
        pn[tid]  = valid ? fabsf(pnb[p*MM + tid]) : 0.f;
    }
    __syncthreads();
    float den = 1e-8f;
    #pragma unroll
    for (int m = 0; m < MM; m++) den += pn[m];
    const float inv = 1.f / den;

    for (int idx = tid; idx < BB*C1; idx += 128) {
        int b = idx >> 6, c = idx & 63;
        float acc = 0.f;
        #pragma unroll
        for (int m = 0; m < MM; m++)
            acc += pn[m] * h1[((long)b*P0 + nbs[m])*C1 + c];
        h2[((long)b*P1 + p)*C1 + c] = eluf(acc * inv);
    }
}

// ---------------- stage 3a: s2 -> split-bf16 A, direct-from-L2 gather ----------------
// thread (b, channel-pair ip): loads its 10 neighbor f32x2 straight from h2
// (coalesced 256B per warp per m), accumulates 9 taps, emits Ah/Al bf16.
__global__ void __launch_bounds__(256) k_s2(
    const float* __restrict__ h2, const int* __restrict__ nb2,
    const float* __restrict__ ww2,
    __nv_bfloat16* __restrict__ Ah, __nv_bfloat16* __restrict__ Al)
{
    __shared__ ull w2p[MM][WW];   // packed (w,w) f32x2 weights
    __shared__ int nbs[MM];
    const int p = blockIdx.x, tid = threadIdx.x;
    if (tid < MM) {
        int nb = nb2[p*MM + tid];
        bool valid = (nb != P1);
        nbs[tid] = valid ? nb : 0;
        const float* wp = ww2 + ((long)p*MM + tid)*WW;
        #pragma unroll
        for (int w = 0; w < WW; w++) {
            float wv = valid ? wp[w] : 0.f;
            w2p[tid][w] = pk2(wv, wv);
        }
    }
    __syncthreads();

    const int b  = tid >> 5;          // 0..7
    const int ip = tid & 31;          // channel pair, i = 2*ip

    ull v[MM];
    #pragma unroll
    for (int m = 0; m < MM; m++)
        v[m] = *(const ull*)(h2 + ((long)b*P1 + nbs[m])*C1 + 2*ip);

    const long rbase = (long)(b*P1 + p)*KA3 + 2*ip;
    #pragma unroll
    for (int w = 0; w < WW; w++) {
        ull acc = 0ULL;
        #pragma unroll
        for (int m = 0; m < MM; m++) fma2(acc, w2p[m][w], v[m]);
        float2 f = upk2(acc);
        uint32_t hi = bfpack(f.x, f.y);
        __nv_bfloat162 hv = *(__nv_bfloat162*)&hi;
        uint32_t lo = bfpack(f.x - __bfloat162float(hv.x),
                             f.y - __bfloat162float(hv.y));
        *(uint32_t*)(Ah + rbase + w*C1) = hi;
        *(uint32_t*)(Al + rbase + w*C1) = lo;
    }
}

// ---------------- B prep: BTh/BTl[o][w*64+i] bf16 split ----------------
__global__ void k_bprep(const float* __restrict__ w2g,
                        __nv_bfloat16* __restrict__ BTh,
                        __nv_bfloat16* __restrict__ BTl){
    int k = blockIdx.x;   // 576
    int o = threadIdx.x;  // 128
    int w = k >> 6, i = k & 63;
    float v = w2g[w*(C2*C1) + o*C1 + i];
    __nv_bfloat16 hv = __float2bfloat16(v);
    BTh[o*KA3 + k] = hv;
    BTl[o*KA3 + k] = __float2bfloat16(v - __bfloat162float(hv));
}

// ---------------- stage 3b: HMMA split-bf16 GEMM + bias + elu ----------------
// smem per buffer (64KB): AH 16K | AL 16K | BH 16K | BL 16K, fragment-packed.
#define MMA_SMEM (2*65536)

#define MMA_BF16(c, a, b) \
    asm volatile("mma.sync.aligned.m16n8k16.row.col.f32.bf16.bf16.f32 " \
        "{%0,%1,%2,%3}, {%4,%5,%6,%7}, {%8,%9}, {%0,%1,%2,%3};" \
        : "+f"(c[0]), "+f"(c[1]), "+f"(c[2]), "+f"(c[3]) \
        : "r"(a.x), "r"(a.y), "r"(a.z), "r"(a.w), "r"(b.x), "r"(b.y))

__global__ void __launch_bounds__(256) k_mma(
    const __nv_bfloat16* __restrict__ Ah, const __nv_bfloat16* __restrict__ Al,
    const __nv_bfloat16* __restrict__ BTh, const __nv_bfloat16* __restrict__ BTl,
    const float* __restrict__ bias, float* __restrict__ C)
{
    extern __shared__ __align__(16) char sm[];
    const int tid = threadIdx.x;
    const int wid = tid >> 5, lane = tid & 31;
    const int mw = wid & 3, nw = wid >> 2;
    const long r0 = (long)blockIdx.x * GBM;

    float c[2][8][4];
    #pragma unroll
    for (int rb = 0; rb < 2; rb++)
        #pragma unroll
        for (int j = 0; j < 8; j++)
            #pragma unroll
            for (int q = 0; q < 4; q++) c[rb][j][q] = 0.f;

    const int g = lane >> 2, tc = lane & 3;

    #define STAGE_CHUNK(kc, bufo) do {                                          \
        const __nv_bfloat16* Ahb = Ah + r0*KA3 + (kc)*64;                       \
        const __nv_bfloat16* Alb = Al + r0*KA3 + (kc)*64;                       \
        const __nv_bfloat16* Bhb = BTh + (kc)*64;                               \
        const __nv_bfloat16* Blb = BTl + (kc)*64;                               \
        _Pragma("unroll")                                                       \
        for (int it = 0; it < 16; it++) {                                       \
            int idx = tid + it*256;                                             \
            int row = idx >> 5, p = idx & 31;                                   \
            uint32_t hi = *(const uint32_t*)(Ahb + (long)row*KA3 + 2*p);        \
            uint32_t lo = *(const uint32_t*)(Alb + (long)row*KA3 + 2*p);        \
            int kstep = p >> 3, pl = p & 7, tcc = pl & 3, ksel = pl >> 2;       \
            int rblk = row >> 4, r16 = row & 15, gg = r16 & 7, half = r16 >> 3; \
            int reg = ksel*2 + half, ln = gg*4 + tcc;                           \
            uint32_t* dst = (uint32_t*)(sm + (bufo) + (kstep*8 + rblk)*512) + ln*4 + reg; \
            dst[0] = hi;                                                        \
            *(uint32_t*)((char*)dst + 16384) = lo;                              \
        }                                                                       \
        _Pragma("unroll")                                                       \
        for (int it = 0; it < 16; it++) {                                       \
            int idx = tid + it*256;                                             \
            int n = idx >> 5, p = idx & 31;                                     \
            uint32_t hi = *(const uint32_t*)(Bhb + (long)n*KA3 + 2*p);          \
            uint32_t lo = *(const uint32_t*)(Blb + (long)n*KA3 + 2*p);          \
            int kstep = p >> 3, pl = p & 7, tcc = pl & 3, ksel = pl >> 2;       \
            int nblk = n >> 3, gg = n & 7;                                      \
            int ln = gg*4 + tcc;                                                \
            uint32_t* dst = (uint32_t*)(sm + (bufo) + 32768 + (kstep*16 + nblk)*256) + ln*2 + ksel; \
            dst[0] = hi;                                                        \
            *(uint32_t*)((char*)dst + 16384) = lo;                              \
        }                                                                       \
    } while(0)

    STAGE_CHUNK(0, 0);
    __syncthreads();

    const int rblk0 = mw*2, rblk1 = mw*2 + 1;
    const int nblk0 = nw*8;
    int bufo = 0;

    for (int kc = 0; kc < 9; kc++) {
        if (kc + 1 < 9) STAGE_CHUNK(kc + 1, bufo ^ 65536);
        const char* sb = sm + bufo;
        #pragma unroll
        for (int ks = 0; ks < 4; ks++) {
            uint4 ah0 = *(const uint4*)(sb + (ks*8 + rblk0)*512 + lane*16);
            uint4 ah1 = *(const uint4*)(sb + (ks*8 + rblk1)*512 + lane*16);
            uint4 al0 = *(const uint4*)(sb + 16384 + (ks*8 + rblk0)*512 + lane*16);
            uint4 al1 = *(const uint4*)(sb + 16384 + (ks*8 + rblk1)*512 + lane*16);
            uint2 bh[8], bl[8];
            #pragma unroll
            for (int j = 0; j < 8; j++) {
                bh[j] = *(const uint2*)(sb + 32768 + (ks*16 + nblk0 + j)*256 + lane*8);
                bl[j] = *(const uint2*)(sb + 49152 + (ks*16 + nblk0 + j)*256 + lane*8);
            }
            #pragma unroll
            for (int j = 0; j < 8; j++) { MMA_BF16(c[0][j], ah0, bh[j]); MMA_BF16(c[1][j], ah1, bh[j]); }
            #pragma unroll
            for (int j = 0; j < 8; j++) { MMA_BF16(c[0][j], ah0, bl[j]); MMA_BF16(c[1][j], ah1, bl[j]); }
            #pragma unroll
            for (int j = 0; j < 8; j++) { MMA_BF16(c[0][j], al0, bh[j]); MMA_BF16(c[1][j], al1, bh[j]); }
        }
        __syncthreads();
        bufo ^= 65536;
    }

    // epilogue: bias + elu
    #pragma unroll
    for (int rb = 0; rb < 2; rb++) {
        long row0 = r0 + (mw*2 + rb)*16 + g;
        long row1 = row0 + 8;
        #pragma unroll
        for (int j = 0; j < 8; j++) {
            int col = nw*64 + j*8 + tc*2;
            float2 bia = *(const float2*)(bias + col);
            if (row0 < NROWS) {
                float2 o;
                o.x = eluf(c[rb][j][0] + bia.x);
                o.y = eluf(c[rb][j][1] + bia.y);
                *(float2*)&C[row0*C2 + col] = o;
            }
            if (row1 < NROWS) {
                float2 o;
                o.x = eluf(c[rb][j][2] + bia.x);
                o.y = eluf(c[rb][j][3] + bia.y);
                *(float2*)&C[row1*C2 + col] = o;
            }
        }
    }
    #undef STAGE_CHUNK
}

// ---------------- stage 4: pool3 + elu, writes f TRANSPOSED ft[k][b] ----------------
__global__ void __launch_bounds__(128) k_pool3(
    const float* __restrict__ h3, const int* __restrict__ nb3,
    const float* __restrict__ pnb, float* __restrict__ ft)
{
    __shared__ float pn[MM];
    __shared__ int nbs[MM];
    const int p = blockIdx.x, tid = threadIdx.x;
    if (tid < MM) {
        int nb = nb3[p*MM + tid];
        bool valid = (nb != P1);
        nbs[tid] = valid ? nb : 0;
        pn[tid]  = valid ? fabsf(pnb[p*MM + tid]) : 0.f;
    }
    __syncthreads();
    float den = 1e-8f;
    #pragma unroll
    for (int m = 0; m < MM; m++) den += pn[m];
    const float inv = 1.f / den;
    const int c = tid;
    float out[BB];
    #pragma unroll
    for (int b = 0; b < BB; b++) {
        float acc = 0.f;
        #pragma unroll
        for (int m = 0; m < MM; m++)
            acc += pn[m] * h3[((long)b*P1 + nbs[m])*C2 + c];
        out[b] = eluf(acc * inv);
    }
    float4* d = (float4*)(ft + ((long)p*C2 + c)*BB);
    d[0] = make_float4(out[0], out[1], out[2], out[3]);
    d[1] = make_float4(out[4], out[5], out[6], out[7]);
}

// ---------------- stage 5: dense head ----------------
__global__ void __launch_bounds__(256) k_dense(
    const float* __restrict__ Wm, const float* __restrict__ Ws,
    const float* __restrict__ ft, float* __restrict__ part)
{
    extern __shared__ float fs[];
    const int tid = threadIdx.x;
    const int rb = blockIdx.x & 15;
    const int sk = blockIdx.x >> 4;
    const int kbase = sk * DKS;

    {
        const float4* src = (const float4*)(ft + (long)kbase*BB);
        float4* dst = (float4*)fs;
        for (int i = tid; i < DKS*BB/4; i += 256) dst[i] = src[i];
    }
    __syncthreads();

    const int warp = tid >> 5, lane = tid & 31;
    const int l0 = rb*32 + warp*4;
    const float* Wb = (l0 < LATENT) ? (Wm + (long)l0*FDIM)
                                    : (Ws + (long)(l0 - LATENT)*FDIM);
    const float* W0 = Wb;
    const float* W1 = Wb + FDIM;
    const float* W2p = Wb + 2L*FDIM;
    const float* W3 = Wb + 3L*FDIM;

    const int kl = lane >> 1;
    const int h  = lane & 1;
    const float* fpb = fs + h*4;

    ull a00=0,a01=0,a10=0,a11=0,a20=0,a21=0,a30=0,a31=0;

    #pragma unroll 2
    for (int t = 0; t < DKS/16; t++) {
        int k = t*16 + kl;
        float4 fv = *(const float4*)(fpb + k*8);
        ull f01 = pk2(fv.x, fv.y);
        ull f23 = pk2(fv.z, fv.w);
        long kg = kbase + k;
        float w0 = W0[kg], w1 = W1[kg], w2v = W2p[kg], w3 = W3[kg];
        ull p0 = pk2(w0,w0), p1 = pk2(w1,w1), p2 = pk2(w2v,w2v), p3 = pk2(w3,w3);
        fma2(a00,p0,f01); fma2(a01,p0,f23);
        fma2(a10,p1,f01); fma2(a11,p1,f23);
        fma2(a20,p2,f01); fma2(a21,p2,f23);
        fma2(a30,p3,f01); fma2(a31,p3,f23);
    }

    #pragma unroll
    for (int ofs = 2; ofs < 32; ofs <<= 1) {
        a00 = add2(a00, __shfl_xor_sync(0xffffffffu, a00, ofs));
        a01 = add2(a01, __shfl_xor_sync(0xffffffffu, a01, ofs));
        a10 = add2(a10, __shfl_xor_sync(0xffffffffu, a10, ofs));
        a11 = add2(a11, __shfl_xor_sync(0xffffffffu, a11, ofs));
        a20 = add2(a20, __shfl_xor_sync(0xffffffffu, a20, ofs));
        a21 = add2(a21, __shfl_xor_sync(0xffffffffu, a21, ofs));
        a30 = add2(a30, __shfl_xor_sync(0xffffffffu, a30, ofs));
        a31 = add2(a31, __shfl_xor_sync(0xffffffffu, a31, ofs));
    }

    if (kl == 0) {
        float* dst = part + ((long)sk*512 + l0)*BB + h*4;
        float2 v;
        v=upk2(a00); dst[0]=v.x; dst[1]=v.y; v=upk2(a01); dst[2]=v.x; dst[3]=v.y;
        dst += BB;
        v=upk2(a10); dst[0]=v.x; dst[1]=v.y; v=upk2(a11); dst[2]=v.x; dst[3]=v.y;
        dst += BB;
        v=upk2(a20); dst[0]=v.x; dst[1]=v.y; v=upk2(a21); dst[2]=v.x; dst[3]=v.y;
        dst += BB;
        v=upk2(a30); dst[0]=v.x; dst[1]=v.y; v=upk2(a31); dst[2]=v.x; dst[3]=v.y;
    }
}

__global__ void __launch_bounds__(256) k_reduce(
    const float* __restrict__ part, const float* __restrict__ bm,
    const float* __restrict__ bs, float* __restrict__ out)
{
    int idx = blockIdx.x*256 + threadIdx.x;
    int l = idx >> 3, b = idx & 7;
    float acc = (l < LATENT) ? bm[l] : bs[l - LATENT];
    for (int sk = 0; sk < SPLITD; sk++) acc += part[((long)sk*512 + l)*BB + b];
    out[b*512 + l] = acc;
}

// ---------------- launch ----------------
extern "C" void kernel_launch(void* const* d_in, const int* in_sizes, int n_in,
                              void* d_out, int out_size)
{
    const float* x      = (const float*)d_in[0];
    const int*   nb0    = (const int*)  d_in[1];
    const int*   nb1    = (const int*)  d_in[2];
    const int*   nb2    = (const int*)  d_in[3];
    const int*   nb3    = (const int*)  d_in[4];
    const float* w0     = (const float*)d_in[5];
    const float* bias0  = (const float*)d_in[6];
    const float* ww0    = (const float*)d_in[7];
    const float* pnb1   = (const float*)d_in[8];
    const float* w2     = (const float*)d_in[9];
    const float* bias2  = (const float*)d_in[10];
    const float* ww2    = (const float*)d_in[11];
    const float* pnb3   = (const float*)d_in[12];
    const float* Wm     = (const float*)d_in[13];
    const float* bm     = (const float*)d_in[14];
    const float* Ws     = (const float*)d_in[15];
    const float* bs     = (const float*)d_in[16];
    float* out = (float*)d_out;

    float *h1, *h2, *h3, *ft, *part;
    __nv_bfloat16 *Ah, *Al, *BTh, *BTl;
    cudaGetSymbolAddress((void**)&h1,   g_h1);
    cudaGetSymbolAddress((void**)&h2,   g_h2);
    cudaGetSymbolAddress((void**)&Ah,   g_Ah);
    cudaGetSymbolAddress((void**)&Al,   g_Al);
    cudaGetSymbolAddress((void**)&BTh,  g_BTh);
    cudaGetSymbolAddress((void**)&BTl,  g_BTl);
    cudaGetSymbolAddress((void**)&h3,   g_h3);
    cudaGetSymbolAddress((void**)&ft,   g_ft);
    cudaGetSymbolAddress((void**)&part, g_part);

    cudaFuncSetAttribute(k_mma, cudaFuncAttributeMaxDynamicSharedMemorySize, MMA_SMEM);
    cudaFuncSetAttribute(k_dense, cudaFuncAttributeMaxDynamicSharedMemorySize, DKS*BB*4);

    k_bprep <<<KA3, C2>>>(w2, BTh, BTl);
    k_conv0 <<<P0/4, 256>>>(x, nb0, w0, bias0, ww0, h1);
    k_pool1 <<<P1, 128>>>(h1, nb1, pnb1, h2);
    k_s2    <<<P1, 256>>>(h2, nb2, ww2, Ah, Al);
    k_mma   <<<NBLK, 256, MMA_SMEM>>>(Ah, Al, BTh, BTl, bias2, h3);
    k_pool3 <<<P2, 128>>>(h3, nb3, pnb3, ft);
    k_dense <<<16*SPLITD, 256, DKS*BB*4>>>(Wm, Ws, ft, part);
    k_reduce<<<16, 256>>>(part, bm, bs, out);
}

// round 16
// speedup vs baseline: 2.0630x; 1.0552x over previous
#include <cuda_runtime.h>
#include <cuda_bf16.h>
#include <cstdint>

// Shapes
#define BB 8
#define P0 20000
#define P1 5000
#define P2 1250
#define MM 10
#define WW 9
#define C0 3
#define C1 64
#define C2 128
#define LATENT 256
#define FDIM (P2*C2)      // 160000
#define KA3 (WW*C1)       // 576
#define NROWS (BB*P1)     // 40000
#define GBM 128
#define NBLK 313          // ceil(40000/128)
#define AROWS (NBLK*GBM)  // 40064 (padded rows stay zero; stores guarded)

typedef unsigned long long ull;

// ---------------- scratch (device globals; no allocation) ----------------
__device__ float g_h1[BB*P0*C1];        // 10.24M
__device__ float g_h2[BB*P1*C1];        // 2.56M
__device__ __nv_bfloat16 g_Ah[(long)AROWS*KA3];   // 46MB
__device__ __nv_bfloat16 g_Al[(long)AROWS*KA3];   // 46MB
__device__ __nv_bfloat16 g_BTh[C2*KA3];
__device__ __nv_bfloat16 g_BTl[C2*KA3];
__device__ float g_h3[BB*P1*C2];        // 5.12M
__device__ float g_ft[FDIM*BB];         // 1.28M  (f transposed: [k][b])
#define SPLITD 100
#define DKS    1600                      // FDIM / SPLITD
__device__ float g_part[SPLITD*512*BB];  // 409600

__device__ __forceinline__ float eluf(float x){
    return x > 0.f ? x : (expf(x) - 1.f);
}

// ---------------- packed f32x2 helpers ----------------
__device__ __forceinline__ ull pk2(float lo, float hi){
    ull r; asm("mov.b64 %0, {%1,%2};" : "=l"(r) : "f"(lo), "f"(hi)); return r;
}
__device__ __forceinline__ void fma2(ull &d, ull a, ull b){
    asm("fma.rn.f32x2 %0, %1, %2, %0;" : "+l"(d) : "l"(a), "l"(b));
}
__device__ __forceinline__ ull add2(ull a, ull b){
    ull r; asm("add.rn.f32x2 %0, %1, %2;" : "=l"(r) : "l"(a), "l"(b)); return r;
}
__device__ __forceinline__ float2 upk2(ull v){
    float2 f; asm("mov.b64 {%0,%1}, %2;" : "=f"(f.x), "=f"(f.y) : "l"(v)); return f;
}
// pack two bf16 (from floats) into b32: lo = a, hi = b
__device__ __forceinline__ uint32_t bfpack(float a, float b){
    __nv_bfloat162 h = __floats2bfloat162_rn(a, b);
    return *(uint32_t*)&h;
}

// ---------------- stage 1: full_conv0 + elu ----------------
__global__ void __launch_bounds__(256) k_conv0(
    const float* __restrict__ x, const int* __restrict__ nb0,
    const float* __restrict__ w0, const float* __restrict__ bias0,
    const float* __restrict__ ww0, float* __restrict__ h1)
{
    const int PTS = 4;
    __shared__ float sw0[WW*C1*C0];
    __shared__ float nbh[PTS][BB][MM][C0];
    __shared__ float w2s[PTS][MM][WW];
    __shared__ float ssh[PTS][BB][28];
    __shared__ int   nbs[PTS][MM];

    const int tid = threadIdx.x;
    const int p0 = blockIdx.x * PTS;

    for (int i = tid; i < WW*C1*C0; i += 256) sw0[i] = w0[i];

    if (tid < PTS*MM) {
        int pt = tid / MM, m = tid % MM;
        int nb = nb0[(p0+pt)*MM + m];
        bool valid = (nb != P0);
        nbs[pt][m] = valid ? nb : 0;
        const float* wp = ww0 + ((long)(p0+pt)*MM + m)*WW;
        #pragma unroll
        for (int w = 0; w < WW; w++) w2s[pt][m][w] = valid ? wp[w] : 0.f;
    }
    __syncthreads();

    for (int idx = tid; idx < PTS*BB*MM; idx += 256) {
        int pt = idx / (BB*MM); int rem = idx % (BB*MM);
        int b = rem / MM, m = rem % MM;
        const float* xr = x + ((long)b*P0 + nbs[pt][m]) * C0;
        nbh[pt][b][m][0] = xr[0];
        nbh[pt][b][m][1] = xr[1];
        nbh[pt][b][m][2] = xr[2];
    }
    __syncthreads();

    for (int idx = tid; idx < PTS*BB*27; idx += 256) {
        int pt = idx / (BB*27); int rem = idx % (BB*27);
        int b = rem / 27, k = rem % 27;
        int w = k / 3, i = k % 3;
        float acc = 0.f;
        #pragma unroll
        for (int m = 0; m < MM; m++) acc += w2s[pt][m][w] * nbh[pt][b][m][i];
        ssh[pt][b][k] = acc;
    }
    __syncthreads();

    const int o = tid & 63;
    float wr[27];
    #pragma unroll
    for (int k = 0; k < 27; k++) {
        int w = k / 3, i = k % 3;
        wr[k] = sw0[w*(C1*C0) + o*3 + i];
    }
    const float bv = bias0[o];
    const int pairbase = tid >> 6;
    #pragma unroll
    for (int j = 0; j < 8; j++) {
        int pair = pairbase + j*4;
        int pt = pair >> 3, b = pair & 7;
        float acc = bv;
        #pragma unroll
        for (int k = 0; k < 27; k++) acc += wr[k] * ssh[pt][b][k];
        h1[((long)b*P0 + p0 + pt)*C1 + o] = eluf(acc);
    }
}

// ---------------- stage 2: pool1 + elu ----------------
__global__ void __launch_bounds__(128) k_pool1(
    const float* __restrict__ h1, const int* __restrict__ nb1,
    const float* __restrict__ pnb, float* __restrict__ h2)
{
    __shared__ float pn[MM];
    __shared__ int nbs[MM];
    const int p = blockIdx.x, tid = threadIdx.x;
    if (tid < MM) {
        int nb = nb1[p*MM + tid];
        bool valid = (nb != P0);
        nbs[tid] = valid ? nb : 0;
        pn[tid]  = valid ? fabsf(pnb[p*MM + tid]) : 0.f;
    }
    __syncthreads();
    float den = 1e-8f;
    #pragma unroll
    for (int m = 0; m < MM; m++) den += pn[m];
    const float inv = 1.f / den;

    for (int idx = tid; idx < BB*C1; idx += 128) {
        int b = idx >> 6, c = idx & 63;
        float acc = 0.f;
        #pragma unroll
        for (int m = 0; m < MM; m++)
            acc += pn[m] * h1[((long)b*P0 + nbs[m])*C1 + c];
        h2[((long)b*P1 + p)*C1 + c] = eluf(acc * inv);
    }
}

// ---------------- stage 3a: s2 -> split-bf16 A, direct-from-L2 gather ----------------
__global__ void __launch_bounds__(256) k_s2(
    const float* __restrict__ h2, const int* __restrict__ nb2,
    const float* __restrict__ ww2,
    __nv_bfloat16* __restrict__ Ah, __nv_bfloat16* __restrict__ Al)
{
    __shared__ ull w2p[MM][WW];   // packed (w,w) f32x2 weights
    __shared__ int nbs[MM];
    const int p = blockIdx.x, tid = threadIdx.x;
    if (tid < MM) {
        int nb = nb2[p*MM + tid];
        bool valid = (nb != P1);
        nbs[tid] = valid ? nb : 0;
        const float* wp = ww2 + ((long)p*MM + tid)*WW;
        #pragma unroll
        for (int w = 0; w < WW; w++) {
            float wv = valid ? wp[w] : 0.f;
            w2p[tid][w] = pk2(wv, wv);
        }
    }
    __syncthreads();

    const int b  = tid >> 5;          // 0..7
    const int ip = tid & 31;          // channel pair, i = 2*ip

    ull v[MM];
    #pragma unroll
    for (int m = 0; m < MM; m++)
        v[m] = *(const ull*)(h2 + ((long)b*P1 + nbs[m])*C1 + 2*ip);

    const long rbase = (long)(b*P1 + p)*KA3 + 2*ip;
    #pragma unroll
    for (int w = 0; w < WW; w++) {
        ull acc = 0ULL;
        #pragma unroll
        for (int m = 0; m < MM; m++) fma2(acc, w2p[m][w], v[m]);
        float2 f = upk2(acc);
        uint32_t hi = bfpack(f.x, f.y);
        __nv_bfloat162 hv = *(__nv_bfloat162*)&hi;
        uint32_t lo = bfpack(f.x - __bfloat162float(hv.x),
                             f.y - __bfloat162float(hv.y));
        *(uint32_t*)(Ah + rbase + w*C1) = hi;
        *(uint32_t*)(Al + rbase + w*C1) = lo;
    }
}

// ---------------- B prep: BTh/BTl[o][w*64+i] bf16 split ----------------
__global__ void k_bprep(const float* __restrict__ w2g,
                        __nv_bfloat16* __restrict__ BTh,
                        __nv_bfloat16* __restrict__ BTl){
    int k = blockIdx.x;   // 576
    int o = threadIdx.x;  // 128
    int w = k >> 6, i = k & 63;
    float v = w2g[w*(C2*C1) + o*C1 + i];
    __nv_bfloat16 hv = __float2bfloat16(v);
    BTh[o*KA3 + k] = hv;
    BTl[o*KA3 + k] = __float2bfloat16(v - __bfloat162float(hv));
}

// ---------------- stage 3b: HMMA split-bf16 GEMM + bias + elu ----------------
// K-chunk 32: per buffer 32KB {AH 8K | AL 8K | BH 8K | BL 8K}, double-buffered 64KB
// -> 2 CTAs/SM (16 warps) for latency hiding.
#define MMA_SMEM (2*32768)

#define MMA_BF16(c, a, b) \
    asm volatile("mma.sync.aligned.m16n8k16.row.col.f32.bf16.bf16.f32 " \
        "{%0,%1,%2,%3}, {%4,%5,%6,%7}, {%8,%9}, {%0,%1,%2,%3};" \
        : "+f"(c[0]), "+f"(c[1]), "+f"(c[2]), "+f"(c[3]) \
        : "r"(a.x), "r"(a.y), "r"(a.z), "r"(a.w), "r"(b.x), "r"(b.y))

__global__ void __launch_bounds__(256, 2) k_mma(
    const __nv_bfloat16* __restrict__ Ah, const __nv_bfloat16* __restrict__ Al,
    const __nv_bfloat16* __restrict__ BTh, const __nv_bfloat16* __restrict__ BTl,
    const float* __restrict__ bias, float* __restrict__ C)
{
    extern __shared__ __align__(16) char sm[];
    const int tid = threadIdx.x;
    const int wid = tid >> 5, lane = tid & 31;
    const int mw = wid & 3, nw = wid >> 2;
    const long r0 = (long)blockIdx.x * GBM;

    float c[2][8][4];
    #pragma unroll
    for (int rb = 0; rb < 2; rb++)
        #pragma unroll
        for (int j = 0; j < 8; j++)
            #pragma unroll
            for (int q = 0; q < 4; q++) c[rb][j][q] = 0.f;

    const int g = lane >> 2, tc = lane & 3;

    // chunk = 32 k-values = 16 bf16-pairs per row
    #define STAGE_CHUNK(kc, bufo) do {                                          \
        const __nv_bfloat16* Ahb = Ah + r0*KA3 + (kc)*32;                       \
        const __nv_bfloat16* Alb = Al + r0*KA3 + (kc)*32;                       \
        const __nv_bfloat16* Bhb = BTh + (kc)*32;                               \
        const __nv_bfloat16* Blb = BTl + (kc)*32;                               \
        _Pragma("unroll")                                                       \
        for (int it = 0; it < 8; it++) {                                        \
            int idx = tid + it*256;                                             \
            int row = idx >> 4, p = idx & 15;                                   \
            uint32_t hi = *(const uint32_t*)(Ahb + (long)row*KA3 + 2*p);        \
            uint32_t lo = *(const uint32_t*)(Alb + (long)row*KA3 + 2*p);        \
            int kstep = p >> 3, pl = p & 7, tcc = pl & 3, ksel = pl >> 2;       \
            int rblk = row >> 4, r16 = row & 15, gg = r16 & 7, half = r16 >> 3; \
            int reg = ksel*2 + half, ln = gg*4 + tcc;                           \
            uint32_t* dst = (uint32_t*)(sm + (bufo) + (kstep*8 + rblk)*512) + ln*4 + reg; \
            dst[0] = hi;                                                        \
            *(uint32_t*)((char*)dst + 8192) = lo;                               \
        }                                                                       \
        _Pragma("unroll")                                                       \
        for (int it = 0; it < 8; it++) {                                        \
            int idx = tid + it*256;                                             \
            int n = idx >> 4, p = idx & 15;                                     \
            uint32_t hi = *(const uint32_t*)(Bhb + (long)n*KA3 + 2*p);          \
            uint32_t lo = *(const uint32_t*)(Blb + (long)n*KA3 + 2*p);          \
            int kstep = p >> 3, pl = p & 7, tcc = pl & 3, ksel = pl >> 2;       \
            int nblk = n >> 3, gg = n & 7;                                      \
            int ln = gg*4 + tcc;                                                \
            uint32_t* dst = (uint32_t*)(sm + (bufo) + 16384 + (kstep*16 + nblk)*256) + ln*2 + ksel; \
            dst[0] = hi;                                                        \
            *(uint32_t*)((char*)dst + 8192) = lo;                               \
        }                                                                       \
    } while(0)

    STAGE_CHUNK(0, 0);
    __syncthreads();

    const int rblk0 = mw*2, rblk1 = mw*2 + 1;
    const int nblk0 = nw*8;
    int bufo = 0;

    for (int kc = 0; kc < 18; kc++) {
        if (kc + 1 < 18) STAGE_CHUNK(kc + 1, bufo ^ 32768);
        const char* sb = sm + bufo;
        #pragma unroll
        for (int ks = 0; ks < 2; ks++) {
            uint4 ah0 = *(const uint4*)(sb + (ks*8 + rblk0)*512 + lane*16);
            uint4 ah1 = *(const uint4*)(sb + (ks*8 + rblk1)*512 + lane*16);
            uint4 al0 = *(const uint4*)(sb + 8192 + (ks*8 + rblk0)*512 + lane*16);
            uint4 al1 = *(const uint4*)(sb + 8192 + (ks*8 + rblk1)*512 + lane*16);
            uint2 bh[8], bl[8];
            #pragma unroll
            for (int j = 0; j < 8; j++) {
                bh[j] = *(const uint2*)(sb + 16384 + (ks*16 + nblk0 + j)*256 + lane*8);
                bl[j] = *(const uint2*)(sb + 24576 + (ks*16 + nblk0 + j)*256 + lane*8);
            }
            #pragma unroll
            for (int j = 0; j < 8; j++) { MMA_BF16(c[0][j], ah0, bh[j]); MMA_BF16(c[1][j], ah1, bh[j]); }
            #pragma unroll
            for (int j = 0; j < 8; j++) { MMA_BF16(c[0][j], ah0, bl[j]); MMA_BF16(c[1][j], ah1, bl[j]); }
            #pragma unroll
            for (int j = 0; j < 8; j++) { MMA_BF16(c[0][j], al0, bh[j]); MMA_BF16(c[1][j], al1, bh[j]); }
        }
        __syncthreads();
        bufo ^= 32768;
    }

    // epilogue: bias + elu
    #pragma unroll
    for (int rb = 0; rb < 2; rb++) {
        long row0 = r0 + (mw*2 + rb)*16 + g;
        long row1 = row0 + 8;
        #pragma unroll
        for (int j = 0; j < 8; j++) {
            int col = nw*64 + j*8 + tc*2;
            float2 bia = *(const float2*)(bias + col);
            if (row0 < NROWS) {
                float2 o;
                o.x = eluf(c[rb][j][0] + bia.x);
                o.y = eluf(c[rb][j][1] + bia.y);
                *(float2*)&C[row0*C2 + col] = o;
            }
            if (row1 < NROWS) {
                float2 o;
                o.x = eluf(c[rb][j][2] + bia.x);
                o.y = eluf(c[rb][j][3] + bia.y);
                *(float2*)&C[row1*C2 + col] = o;
            }
        }
    }
    #undef STAGE_CHUNK
}

// ---------------- stage 4: pool3 + elu, writes f TRANSPOSED ft[k][b] ----------------
__global__ void __launch_bounds__(128) k_pool3(
    const float* __restrict__ h3, const int* __restrict__ nb3,
    const float* __restrict__ pnb, float* __restrict__ ft)
{
    __shared__ float pn[MM];
    __shared__ int nbs[MM];
    const int p = blockIdx.x, tid = threadIdx.x;
    if (tid < MM) {
        int nb = nb3[p*MM + tid];
        bool valid = (nb != P1);
        nbs[tid] = valid ? nb : 0;
        pn[tid]  = valid ? fabsf(pnb[p*MM + tid]) : 0.f;
    }
    __syncthreads();
    float den = 1e-8f;
    #pragma unroll
    for (int m = 0; m < MM; m++) den += pn[m];
    const float inv = 1.f / den;
    const int c = tid;
    float out[BB];
    #pragma unroll
    for (int b = 0; b < BB; b++) {
        float acc = 0.f;
        #pragma unroll
        for (int m = 0; m < MM; m++)
            acc += pn[m] * h3[((long)b*P1 + nbs[m])*C2 + c];
        out[b] = eluf(acc * inv);
    }
    float4* d = (float4*)(ft + ((long)p*C2 + c)*BB);
    d[0] = make_float4(out[0], out[1], out[2], out[3]);
    d[1] = make_float4(out[4], out[5], out[6], out[7]);
}

// ---------------- stage 5: dense head ----------------
__global__ void __launch_bounds__(256) k_dense(
    const float* __restrict__ Wm, const float* __restrict__ Ws,
    const float* __restrict__ ft, float* __restrict__ part)
{
    extern __shared__ float fs[];
    const int tid = threadIdx.x;
    const int rb = blockIdx.x & 15;
    const int sk = blockIdx.x >> 4;
    const int kbase = sk * DKS;

    {
        const float4* src = (const float4*)(ft + (long)kbase*BB);
        float4* dst = (float4*)fs;
        for (int i = tid; i < DKS*BB/4; i += 256) dst[i] = src[i];
    }
    __syncthreads();

    const int warp = tid >> 5, lane = tid & 31;
    const int l0 = rb*32 + warp*4;
    const float* Wb = (l0 < LATENT) ? (Wm + (long)l0*FDIM)
                                    : (Ws + (long)(l0 - LATENT)*FDIM);
    const float* W0 = Wb;
    const float* W1 = Wb + FDIM;
    const float* W2p = Wb + 2L*FDIM;
    const float* W3 = Wb + 3L*FDIM;

    const int kl = lane >> 1;
    const int h  = lane & 1;
    const float* fpb = fs + h*4;

    ull a00=0,a01=0,a10=0,a11=0,a20=0,a21=0,a30=0,a31=0;

    #pragma unroll 2
    for (int t = 0; t < DKS/16; t++) {
        int k = t*16 + kl;
        float4 fv = *(const float4*)(fpb + k*8);
        ull f01 = pk2(fv.x, fv.y);
        ull f23 = pk2(fv.z, fv.w);
        long kg = kbase + k;
        float w0 = W0[kg], w1 = W1[kg], w2v = W2p[kg], w3 = W3[kg];
        ull p0 = pk2(w0,w0), p1 = pk2(w1,w1), p2 = pk2(w2v,w2v), p3 = pk2(w3,w3);
        fma2(a00,p0,f01); fma2(a01,p0,f23);
        fma2(a10,p1,f01); fma2(a11,p1,f23);
        fma2(a20,p2,f01); fma2(a21,p2,f23);
        fma2(a30,p3,f01); fma2(a31,p3,f23);
    }

    #pragma unroll
    for (int ofs = 2; ofs < 32; ofs <<= 1) {
        a00 = add2(a00, __shfl_xor_sync(0xffffffffu, a00, ofs));
        a01 = add2(a01, __shfl_xor_sync(0xffffffffu, a01, ofs));
        a10 = add2(a10, __shfl_xor_sync(0xffffffffu, a10, ofs));
        a11 = add2(a11, __shfl_xor_sync(0xffffffffu, a11, ofs));
        a20 = add2(a20, __shfl_xor_sync(0xffffffffu, a20, ofs));
        a21 = add2(a21, __shfl_xor_sync(0xffffffffu, a21, ofs));
        a30 = add2(a30, __shfl_xor_sync(0xffffffffu, a30, ofs));
        a31 = add2(a31, __shfl_xor_sync(0xffffffffu, a31, ofs));
    }

    if (kl == 0) {
        float* dst = part + ((long)sk*512 + l0)*BB + h*4;
        float2 v;
        v=upk2(a00); dst[0]=v.x; dst[1]=v.y; v=upk2(a01); dst[2]=v.x; dst[3]=v.y;
        dst += BB;
        v=upk2(a10); dst[0]=v.x; dst[1]=v.y; v=upk2(a11); dst[2]=v.x; dst[3]=v.y;
        dst += BB;
        v=upk2(a20); dst[0]=v.x; dst[1]=v.y; v=upk2(a21); dst[2]=v.x; dst[3]=v.y;
        dst += BB;
        v=upk2(a30); dst[0]=v.x; dst[1]=v.y; v=upk2(a31); dst[2]=v.x; dst[3]=v.y;
    }
}

__global__ void __launch_bounds__(256) k_reduce(
    const float* __restrict__ part, const float* __restrict__ bm,
    const float* __restrict__ bs, float* __restrict__ out)
{
    int idx = blockIdx.x*256 + threadIdx.x;
    int l = idx >> 3, b = idx & 7;
    float acc = (l < LATENT) ? bm[l] : bs[l - LATENT];
    for (int sk = 0; sk < SPLITD; sk++) acc += part[((long)sk*512 + l)*BB + b];
    out[b*512 + l] = acc;
}

// ---------------- launch ----------------
extern "C" void kernel_launch(void* const* d_in, const int* in_sizes, int n_in,
                              void* d_out, int out_size)
{
    const float* x      = (const float*)d_in[0];
    const int*   nb0    = (const int*)  d_in[1];
    const int*   nb1    = (const int*)  d_in[2];
    const int*   nb2    = (const int*)  d_in[3];
    const int*   nb3    = (const int*)  d_in[4];
    const float* w0     = (const float*)d_in[5];
    const float* bias0  = (const float*)d_in[6];
    const float* ww0    = (const float*)d_in[7];
    const float* pnb1   = (const float*)d_in[8];
    const float* w2     = (const float*)d_in[9];
    const float* bias2  = (const float*)d_in[10];
    const float* ww2    = (const float*)d_in[11];
    const float* pnb3   = (const float*)d_in[12];
    const float* Wm     = (const float*)d_in[13];
    const float* bm     = (const float*)d_in[14];
    const float* Ws     = (const float*)d_in[15];
    const float* bs     = (const float*)d_in[16];
    float* out = (float*)d_out;

    float *h1, *h2, *h3, *ft, *part;
    __nv_bfloat16 *Ah, *Al, *BTh, *BTl;
    cudaGetSymbolAddress((void**)&h1,   g_h1);
    cudaGetSymbolAddress((void**)&h2,   g_h2);
    cudaGetSymbolAddress((void**)&Ah,   g_Ah);
    cudaGetSymbolAddress((void**)&Al,   g_Al);
    cudaGetSymbolAddress((void**)&BTh,  g_BTh);
    cudaGetSymbolAddress((void**)&BTl,  g_BTl);
    cudaGetSymbolAddress((void**)&h3,   g_h3);
    cudaGetSymbolAddress((void**)&ft,   g_ft);
    cudaGetSymbolAddress((void**)&part, g_part);

    cudaFuncSetAttribute(k_mma, cudaFuncAttributeMaxDynamicSharedMemorySize, MMA_SMEM);
    cudaFuncSetAttribute(k_dense, cudaFuncAttributeMaxDynamicSharedMemorySize, DKS*BB*4);

    k_bprep <<<KA3, C2>>>(w2, BTh, BTl);
    k_conv0 <<<P0/4, 256>>>(x, nb0, w0, bias0, ww0, h1);
    k_pool1 <<<P1, 128>>>(h1, nb1, pnb1, h2);
    k_s2    <<<P1, 256>>>(h2, nb2, ww2, Ah, Al);
    k_mma   <<<NBLK, 256, MMA_SMEM>>>(Ah, Al, BTh, BTl, bias2, h3);
    k_pool3 <<<P2, 128>>>(h3, nb3, pnb3, ft);
    k_dense <<<16*SPLITD, 256, DKS*BB*4>>>(Wm, Ws, ft, part);
    k_reduce<<<16, 256>>>(part, bm, bs, out);
}